// round 1
// baseline (speedup 1.0000x reference)
#include <cuda_runtime.h>

#define NS   53        // species
#define ND   54        // state dim
#define NRX  325       // reactions
#define MAXF 16        // max forward-stoich nonzeros per reaction
#define MAXN 24        // max net-stoich nonzeros per reaction
#define BD   128       // threads per block
#define MSTR 56        // padded row stride of augmented matrix
#define RGAS 8.314462618f

// ---- sparse stoichiometry tables (built per launch by prep_kernel) ----
__device__ int   g_fcnt[NRX];
__device__ short g_fidx[NRX][MAXF];
__device__ float g_fval[NRX][MAXF];
__device__ int   g_ncnt[NRX];
__device__ short g_nidx[NRX][MAXN];
__device__ float g_nval[NRX][MAXN];

__global__ void prep_kernel(const float* __restrict__ nuf,
                            const float* __restrict__ nub) {
    int j = blockIdx.x * blockDim.x + threadIdx.x;
    if (j >= NRX) return;
    int cf = 0, cn = 0;
    for (int k = 0; k < NS; k++) {
        float f = nuf[j * NS + k];
        float b = nub[j * NS + k];
        if (f != 0.0f && cf < MAXF) {
            g_fidx[j][cf] = (short)k; g_fval[j][cf] = f; cf++;
        }
        float net = b - f;
        if (net != 0.0f && cn < MAXN) {
            g_nidx[j][cn] = (short)k; g_nval[j][cn] = net; cn++;
        }
    }
    g_fcnt[j] = cf;
    g_ncnt[j] = cn;
}

__global__ __launch_bounds__(BD)
void reactor_kernel(const float* __restrict__ T0,  const float* __restrict__ Pv,
                    const float* __restrict__ Y0,  const float* __restrict__ Wm,
                    const float* __restrict__ nlo, const float* __restrict__ nhi,
                    const float* __restrict__ Tmid,
                    const float* __restrict__ rA,  const float* __restrict__ rB,
                    const float* __restrict__ rE,  const int* __restrict__ nstp,
                    float* __restrict__ out) {
    // augmented Newton matrix [I - dt*J | G], col ND is RHS
    __shared__ float Mm[ND][MSTR];
    __shared__ float yn[ND], ycur[ND], xs[ND];
    __shared__ float Ws[NS], cpR[NS], hmol[NS], dcpR[NS], Ycs[NS], mY[NS];
    __shared__ float Lc[NS], gC[NS], t0a[NS], wd[NS], uu[NS], vv[NS], hQ[NS], tmp[NS];
    __shared__ float sT, sMT, sLnT, sIMW, sRho, sCp, sHu, sHv, sHTw, sDcp, sRcp, sdT, sIp;

    const int tid  = threadIdx.x;
    const int lane = tid & 31;
    const int b    = blockIdx.x;

    const float P = Pv[0];
    const int n_steps = nstp[0];
    const float dt = 1.0e-6f / (float)n_steps;

    for (int k = tid; k < NS; k += BD) {
        Ws[k]     = Wm[k];
        yn[1 + k] = Y0[b * NS + k];
    }
    if (tid == 0) yn[0] = T0[b];
    __syncthreads();

    for (int step = 0; step < n_steps; ++step) {
        for (int i = tid; i < ND; i += BD) ycur[i] = yn[i];
        __syncthreads();

        for (int it = 0; it < 2; ++it) {
            // ---- zero accumulators ----
            for (int idx = tid; idx < ND * (ND + 1); idx += BD)
                Mm[idx / (ND + 1)][idx % (ND + 1)] = 0.0f;
            for (int k = tid; k < NS; k += BD) { wd[k] = 0.0f; uu[k] = 0.0f; vv[k] = 0.0f; }
            if (tid == 0) {
                float Tr = yn[0];
                float Tc = fminf(fmaxf(Tr, 200.0f), 5000.0f);
                sT = Tc;
                sMT = (Tr > 200.0f && Tr < 5000.0f) ? 1.0f : 0.0f;
                sLnT = logf(Tc);
            }
            __syncthreads();

            const float T = sT;
            // ---- per-species thermo ----
            for (int k = tid; k < NS; k += BD) {
                float Yr = yn[1 + k];
                float Yc = fminf(fmaxf(Yr, 0.0f), 1.0f);
                Ycs[k] = Yc;
                mY[k]  = (Yr > 0.0f && Yr < 1.0f) ? 1.0f : 0.0f;
                const float* a = (T < Tmid[k]) ? (nlo + 7 * k) : (nhi + 7 * k);
                float a0 = a[0], a1 = a[1], a2 = a[2], a3 = a[3], a4 = a[4], a5 = a[5];
                float T2 = T * T, T3 = T2 * T, T4 = T2 * T2;
                cpR[k]  = a0 + a1 * T + a2 * T2 + a3 * T3 + a4 * T4;
                float hRT = a0 + a1 * T * 0.5f + a2 * T2 * (1.0f / 3.0f)
                          + a3 * T3 * 0.25f + a4 * T4 * 0.2f + a5 / T;
                hmol[k] = hRT * RGAS * T;
                dcpR[k] = a1 + 2.0f * a2 * T + 3.0f * a3 * T2 + 4.0f * a4 * T3;
                tmp[k]  = Yc / Ws[k];
            }
            __syncthreads();
            if (tid < 32) {
                float s = (lane < NS ? tmp[lane] : 0.0f)
                        + (lane + 32 < NS ? tmp[lane + 32] : 0.0f);
                for (int o = 16; o; o >>= 1) s += __shfl_xor_sync(0xffffffffu, s, o);
                if (lane == 0) { sIMW = s; sRho = P / (RGAS * T * s); }
            }
            __syncthreads();
            const float rho = sRho;
            for (int k = tid; k < NS; k += BD) {
                float C  = rho * Ycs[k] / Ws[k];
                float Ce = C + 1e-30f;
                Lc[k]  = logf(Ce);
                gC[k]  = C / Ce;
                t0a[k] = rho / (Ws[k] * Ce);
            }
            __syncthreads();

            // ---- reaction pass: rates + exact sensitivities ----
            const float RT = RGAS * T;
            for (int j = tid; j < NRX; j += BD) {
                float Aj = rA[j], bj = rB[j], Ej = rE[j];
                float kf = Aj * expf(bj * sLnT - Ej / RT);
                int nf = g_fcnt[j];
                float sL = 0.0f, Pj = 0.0f;
                for (int e = 0; e < nf; e++) {
                    int k = g_fidx[j][e]; float v = g_fval[j][e];
                    sL += v * Lc[k]; Pj += v * gC[k];
                }
                float r  = kf * expf(sL);
                float rT = (r / T) * (bj + Ej / RT - Pj);   // dr/dT (unmasked)
                float rP = r * Pj;
                int nn = g_ncnt[j];
                for (int e = 0; e < nn; e++) {
                    int k = g_nidx[j][e]; float nu = g_nval[j][e];
                    atomicAdd(&wd[k], nu * r);
                    atomicAdd(&uu[k], nu * rP);
                    atomicAdd(&vv[k], nu * rT);
                    float nur = nu * r;
                    for (int e2 = 0; e2 < nf; e2++)
                        atomicAdd(&Mm[k + 1][g_fidx[j][e2] + 1], nur * g_fval[j][e2]);
                }
            }
            __syncthreads();

            // ---- scalar reductions ----
            if (tid < 32) {
                float cp = 0, H = 0, hu = 0, hv = 0, hw = 0, dc = 0;
                for (int k = lane; k < NS; k += 32) {
                    float yw = Ycs[k] / Ws[k];
                    cp += yw * cpR[k];
                    H  += hmol[k] * wd[k];
                    hu += hmol[k] * uu[k];
                    hv += hmol[k] * vv[k];
                    hw += cpR[k] * wd[k];
                    dc += yw * dcpR[k];
                }
                for (int o = 16; o; o >>= 1) {
                    cp += __shfl_xor_sync(0xffffffffu, cp, o);
                    H  += __shfl_xor_sync(0xffffffffu, H,  o);
                    hu += __shfl_xor_sync(0xffffffffu, hu, o);
                    hv += __shfl_xor_sync(0xffffffffu, hv, o);
                    hw += __shfl_xor_sync(0xffffffffu, hw, o);
                    dc += __shfl_xor_sync(0xffffffffu, dc, o);
                }
                if (lane == 0) {
                    float cpm = RGAS * cp;
                    sCp = cpm; sHu = hu; sHv = hv;
                    sHTw = RGAS * hw; sDcp = RGAS * dc;
                    float rcp = rho * cpm;
                    sRcp = rcp;
                    sdT = -H / rcp;
                }
            }
            __syncthreads();

            // ---- hQ_m = sum_k h_k * Qraw[k][m] (before M transform) ----
            for (int m = tid; m < NS; m += BD) {
                float s = 0.0f;
                for (int k = 0; k < NS; k++) s += hmol[k] * Mm[k + 1][m + 1];
                hQ[m] = s;
            }
            __syncthreads();

            // ---- build M = I - dt*J and RHS G ----
            const float invIMW = 1.0f / sIMW;
            const float rcp = sRcp, dTv = sdT, cpm = sCp, huv = sHu;
            for (int idx = tid; idx < NS * NS; idx += BD) {
                int k = idx / NS, m = idx - k * NS;
                float q   = Mm[k + 1][m + 1];            // Qraw_{km}
                float sm0 = -invIMW / Ws[m];             // dln(rho)/dY_m
                float J = mY[m] * (Ws[k] / rho)
                        * ((uu[k] - wd[k]) * sm0 + q * t0a[m]);
                Mm[k + 1][m + 1] = ((k == m) ? 1.0f : 0.0f) - dt * J;
            }
            for (int k = tid; k < NS; k += BD) {
                float Jk0 = sMT * (Ws[k] / rho) * (vv[k] + wd[k] / T);
                Mm[k + 1][0] = -dt * Jk0;
                float sm0 = -invIMW / Ws[k];
                float J0m = mY[k] * (-(huv * sm0 + hQ[k] * t0a[k]) / rcp
                                     - dTv * (sm0 + cpR[k] * RGAS / (Ws[k] * cpm)));
                Mm[0][k + 1] = -dt * J0m;
                float fk = wd[k] * Ws[k] / rho;
                Mm[k + 1][ND] = yn[1 + k] - ycur[1 + k] - dt * fk;
            }
            if (tid == 0) {
                float J00 = sMT * (-(sHTw + sHv) / rcp
                                   - dTv * (-1.0f / T + sDcp / cpm));
                Mm[0][0]  = 1.0f - dt * J00;
                Mm[0][ND] = yn[0] - ycur[0] - dt * dTv;
            }
            __syncthreads();

            // ---- LU with partial pivoting on augmented [M | G] ----
            for (int p = 0; p < ND; p++) {
                if (tid < 32) {
                    int i1 = p + lane, i2 = p + lane + 32;
                    float v1 = (i1 < ND) ? fabsf(Mm[i1][p]) : -1.0f;
                    float v2 = (i2 < ND) ? fabsf(Mm[i2][p]) : -1.0f;
                    float av; int ai;
                    if (v2 > v1) { av = v2; ai = i2; } else { av = v1; ai = i1; }
                    for (int o = 16; o; o >>= 1) {
                        float oa = __shfl_xor_sync(0xffffffffu, av, o);
                        int   oi = __shfl_xor_sync(0xffffffffu, ai, o);
                        if (oa > av || (oa == av && oi < ai)) { av = oa; ai = oi; }
                    }
                    int piv = ai;
                    if (piv != p) {
                        for (int c = p + lane; c <= ND; c += 32) {
                            float t = Mm[p][c]; Mm[p][c] = Mm[piv][c]; Mm[piv][c] = t;
                        }
                    }
                    __syncwarp();
                    if (lane == 0) sIp = 1.0f / Mm[p][p];
                }
                __syncthreads();
                int nr = ND - 1 - p;
                int nc = ND - p;               // cols p+1 .. ND (incl RHS)
                float ip = sIp;
                for (int idx = tid; idx < nr * nc; idx += BD) {
                    int i  = p + 1 + idx / nc;
                    int jj = p + 1 + idx % nc;
                    Mm[i][jj] -= Mm[i][p] * ip * Mm[p][jj];
                }
                __syncthreads();
            }

            // ---- back substitution (warp 0) ----
            if (tid < 32) {
                for (int i = ND - 1; i >= 0; i--) {
                    float s = 0.0f;
                    for (int jj = i + 1 + lane; jj < ND; jj += 32)
                        s += Mm[i][jj] * xs[jj];
                    for (int o = 16; o; o >>= 1) s += __shfl_xor_sync(0xffffffffu, s, o);
                    if (lane == 0) xs[i] = (Mm[i][ND] - s) / Mm[i][i];
                    __syncwarp();
                }
            }
            __syncthreads();
            for (int i = tid; i < ND; i += BD) yn[i] -= xs[i];
            __syncthreads();
        } // newton
    } // steps

    for (int i = tid; i < ND; i += BD) out[b * ND + i] = yn[i];
}

extern "C" void kernel_launch(void* const* d_in, const int* in_sizes, int n_in,
                              void* d_out, int out_size) {
    const float* T0  = (const float*)d_in[0];
    const float* P   = (const float*)d_in[1];
    const float* Y0  = (const float*)d_in[2];
    const float* W   = (const float*)d_in[3];
    const float* nlo = (const float*)d_in[4];
    const float* nhi = (const float*)d_in[5];
    const float* Tm  = (const float*)d_in[6];
    const float* A   = (const float*)d_in[7];
    const float* Bc  = (const float*)d_in[8];
    const float* E   = (const float*)d_in[9];
    const float* nf  = (const float*)d_in[10];
    const float* nb  = (const float*)d_in[11];
    const int*   ns  = (const int*)d_in[12];
    const int B = in_sizes[0];

    prep_kernel<<<(NRX + 127) / 128, 128>>>(nf, nb);
    reactor_kernel<<<B, BD>>>(T0, P, Y0, W, nlo, nhi, Tm, A, Bc, E, ns, (float*)d_out);
}

// round 2
// speedup vs baseline: 1.6039x; 1.6039x over previous
#include <cuda_runtime.h>

#define NS   53        // species
#define ND   54        // state dim
#define NRX  325       // reactions
#define MAXF 16        // max forward-stoich nonzeros per reaction
#define MAXN 24        // max net-stoich nonzeros per reaction
#define BD   128       // threads per block
#define MSTR 56        // padded row stride of augmented matrix
#define RGAS 8.314462618f

// ---- sparse stoichiometry tables (built per launch by prep_kernel) ----
__device__ int   g_fcnt[NRX];
__device__ short g_fidx[NRX][MAXF];
__device__ float g_fval[NRX][MAXF];
__device__ int   g_ncnt[NRX];
__device__ short g_nidx[NRX][MAXN];
__device__ float g_nval[NRX][MAXN];

__global__ void prep_kernel(const float* __restrict__ nuf,
                            const float* __restrict__ nub) {
    int j = blockIdx.x * blockDim.x + threadIdx.x;
    if (j >= NRX) return;
    int cf = 0, cn = 0;
    for (int k = 0; k < NS; k++) {
        float f = nuf[j * NS + k];
        float b = nub[j * NS + k];
        if (f != 0.0f && cf < MAXF) {
            g_fidx[j][cf] = (short)k; g_fval[j][cf] = f; cf++;
        }
        float net = b - f;
        if (net != 0.0f && cn < MAXN) {
            g_nidx[j][cn] = (short)k; g_nval[j][cn] = net; cn++;
        }
    }
    g_fcnt[j] = cf;
    g_ncnt[j] = cn;
}

__global__ __launch_bounds__(BD)
void reactor_kernel(const float* __restrict__ T0,  const float* __restrict__ Pv,
                    const float* __restrict__ Y0,  const float* __restrict__ Wm,
                    const float* __restrict__ nlo, const float* __restrict__ nhi,
                    const float* __restrict__ Tmid,
                    const float* __restrict__ rA,  const float* __restrict__ rB,
                    const float* __restrict__ rE,  const int* __restrict__ nstp,
                    float* __restrict__ out) {
    // augmented Newton matrix [I - dt*J | G], col ND is RHS
    __shared__ __align__(16) float Mm[ND][MSTR];
    __shared__ float yn[ND], ycur[ND], xs[ND];
    __shared__ float Ws[NS], invW[NS], cpR[NS], hmol[NS], dcpR[NS], Ycs[NS], mY[NS];
    __shared__ float Lc[NS], gC[NS], t0a[NS], wd[NS], uu[NS], vv[NS], hQ[NS], tmp[NS];
    __shared__ float Wor[NS], sm0[NS];
    __shared__ float sT, sMT, sLnT, sIMW, sInvIMW, sRho, sInvRho;
    __shared__ float sCp, sHu, sHv, sHTw, sDcp, sRcp, sdT;

    const int tid  = threadIdx.x;
    const int lane = tid & 31;
    const int wid  = tid >> 5;
    const int b    = blockIdx.x;

    const float P = Pv[0];
    const int n_steps = nstp[0];
    const float dt = 1.0e-6f / (float)n_steps;

    for (int k = tid; k < NS; k += BD) {
        float w = Wm[k];
        Ws[k]   = w;
        invW[k] = 1.0f / w;
        yn[1 + k] = Y0[b * NS + k];
    }
    if (tid == 0) yn[0] = T0[b];
    __syncthreads();

    for (int step = 0; step < n_steps; ++step) {
        for (int i = tid; i < ND; i += BD) ycur[i] = yn[i];
        __syncthreads();

        for (int it = 0; it < 2; ++it) {
            // ---- zero accumulators (vectorized) ----
            {
                float4* M4 = (float4*)(&Mm[0][0]);
                const float4 z4 = make_float4(0.f, 0.f, 0.f, 0.f);
                for (int idx = tid; idx < ND * MSTR / 4; idx += BD) M4[idx] = z4;
            }
            for (int k = tid; k < NS; k += BD) { wd[k] = 0.0f; uu[k] = 0.0f; vv[k] = 0.0f; }
            if (tid == 0) {
                float Tr = yn[0];
                float Tc = fminf(fmaxf(Tr, 200.0f), 5000.0f);
                sT = Tc;
                sMT = (Tr > 200.0f && Tr < 5000.0f) ? 1.0f : 0.0f;
                sLnT = logf(Tc);
            }
            __syncthreads();

            const float T = sT;
            const float invT = 1.0f / T;
            // ---- per-species thermo ----
            for (int k = tid; k < NS; k += BD) {
                float Yr = yn[1 + k];
                float Yc = fminf(fmaxf(Yr, 0.0f), 1.0f);
                Ycs[k] = Yc;
                mY[k]  = (Yr > 0.0f && Yr < 1.0f) ? 1.0f : 0.0f;
                const float* a = (T < Tmid[k]) ? (nlo + 7 * k) : (nhi + 7 * k);
                float a0 = a[0], a1 = a[1], a2 = a[2], a3 = a[3], a4 = a[4], a5 = a[5];
                float T2 = T * T, T3 = T2 * T, T4 = T2 * T2;
                cpR[k]  = a0 + a1 * T + a2 * T2 + a3 * T3 + a4 * T4;
                float hRT = a0 + a1 * T * 0.5f + a2 * T2 * (1.0f / 3.0f)
                          + a3 * T3 * 0.25f + a4 * T4 * 0.2f + a5 * invT;
                hmol[k] = hRT * RGAS * T;
                dcpR[k] = a1 + 2.0f * a2 * T + 3.0f * a3 * T2 + 4.0f * a4 * T3;
                tmp[k]  = Yc * invW[k];
            }
            __syncthreads();
            if (tid < 32) {
                float s = (lane < NS ? tmp[lane] : 0.0f)
                        + (lane + 32 < NS ? tmp[lane + 32] : 0.0f);
                for (int o = 16; o; o >>= 1) s += __shfl_xor_sync(0xffffffffu, s, o);
                if (lane == 0) {
                    sIMW = s; sInvIMW = 1.0f / s;
                    float rho = P / (RGAS * T * s);
                    sRho = rho; sInvRho = (RGAS * T * s) / P;
                }
            }
            __syncthreads();
            const float rho = sRho, invRho = sInvRho, invIMW = sInvIMW;
            for (int k = tid; k < NS; k += BD) {
                float iw = invW[k];
                float C  = rho * Ycs[k] * iw;
                float Ce = C + 1e-30f;
                Lc[k]  = logf(Ce);
                gC[k]  = C / Ce;
                t0a[k] = rho * iw / Ce;
                Wor[k] = Ws[k] * invRho;
                sm0[k] = -invIMW * iw;
            }
            __syncthreads();

            // ---- reaction pass: rates + exact sensitivities ----
            const float RT = RGAS * T;
            const float invRT = 1.0f / RT;
            for (int j = tid; j < NRX; j += BD) {
                float Aj = rA[j], bj = rB[j], Ej = rE[j];
                float kf = Aj * expf(bj * sLnT - Ej * invRT);
                int nf = g_fcnt[j];
                float sL = 0.0f, Pj = 0.0f;
                for (int e = 0; e < nf; e++) {
                    int k = g_fidx[j][e]; float v = g_fval[j][e];
                    sL += v * Lc[k]; Pj += v * gC[k];
                }
                float r  = kf * expf(sL);
                float rT = (r * invT) * (bj + Ej * invRT - Pj);   // dr/dT (unmasked)
                float rP = r * Pj;
                int nn = g_ncnt[j];
                for (int e = 0; e < nn; e++) {
                    int k = g_nidx[j][e]; float nu = g_nval[j][e];
                    atomicAdd(&wd[k], nu * r);
                    atomicAdd(&uu[k], nu * rP);
                    atomicAdd(&vv[k], nu * rT);
                    float nur = nu * r;
                    for (int e2 = 0; e2 < nf; e2++)
                        atomicAdd(&Mm[k + 1][g_fidx[j][e2] + 1], nur * g_fval[j][e2]);
                }
            }
            __syncthreads();

            // ---- scalar reductions ----
            if (tid < 32) {
                float cp = 0, H = 0, hu = 0, hv = 0, hw = 0, dc = 0;
                for (int k = lane; k < NS; k += 32) {
                    float yw = Ycs[k] * invW[k];
                    cp += yw * cpR[k];
                    H  += hmol[k] * wd[k];
                    hu += hmol[k] * uu[k];
                    hv += hmol[k] * vv[k];
                    hw += cpR[k] * wd[k];
                    dc += yw * dcpR[k];
                }
                for (int o = 16; o; o >>= 1) {
                    cp += __shfl_xor_sync(0xffffffffu, cp, o);
                    H  += __shfl_xor_sync(0xffffffffu, H,  o);
                    hu += __shfl_xor_sync(0xffffffffu, hu, o);
                    hv += __shfl_xor_sync(0xffffffffu, hv, o);
                    hw += __shfl_xor_sync(0xffffffffu, hw, o);
                    dc += __shfl_xor_sync(0xffffffffu, dc, o);
                }
                if (lane == 0) {
                    float cpm = RGAS * cp;
                    sCp = cpm; sHu = hu; sHv = hv;
                    sHTw = RGAS * hw; sDcp = RGAS * dc;
                    float rcp = rho * cpm;
                    sRcp = rcp;
                    sdT = -H / rcp;
                }
            }
            __syncthreads();

            // ---- hQ_m = sum_k h_k * Qraw[k][m] (before M transform) ----
            for (int m = tid; m < NS; m += BD) {
                float s = 0.0f;
                for (int k = 0; k < NS; k++) s += hmol[k] * Mm[k + 1][m + 1];
                hQ[m] = s;
            }
            __syncthreads();

            // ---- build M = I - dt*J (warp-per-row, lane-per-col) ----
            const float rcp = sRcp, dTv = sdT, cpm = sCp, huv = sHu;
            const float invCpm = 1.0f / cpm, invRcp = 1.0f / rcp;
            for (int k = wid; k < NS; k += 4) {
                float uk  = uu[k] - wd[k];
                float wok = Wor[k];
                for (int m = lane; m < NS; m += 32) {
                    float q = Mm[k + 1][m + 1];            // Qraw_{km}
                    float J = mY[m] * wok * (uk * sm0[m] + q * t0a[m]);
                    Mm[k + 1][m + 1] = ((k == m) ? 1.0f : 0.0f) - dt * J;
                }
            }
            __syncthreads();
            for (int k = tid; k < NS; k += BD) {
                float Jk0 = sMT * Wor[k] * (vv[k] + wd[k] * invT);
                Mm[k + 1][0] = -dt * Jk0;
                float sm0k = sm0[k];
                float J0m = mY[k] * (-(huv * sm0k + hQ[k] * t0a[k]) * invRcp
                                     - dTv * (sm0k + cpR[k] * RGAS * invW[k] * invCpm));
                Mm[0][k + 1] = -dt * J0m;
                float fk = wd[k] * Wor[k];
                Mm[k + 1][ND] = yn[1 + k] - ycur[1 + k] - dt * fk;
            }
            if (tid == 0) {
                float J00 = sMT * (-(sHTw + sHv) / rcp
                                   - dTv * (-invT + sDcp / cpm));
                Mm[0][0]  = 1.0f - dt * J00;
                Mm[0][ND] = yn[0] - ycur[0] - dt * dTv;
            }
            __syncthreads();

            // ---- LU with partial pivoting on augmented [M | G] ----
            for (int p = 0; p < ND; p++) {
                if (tid < 32) {
                    int i1 = p + lane, i2 = p + lane + 32;
                    float v1 = (i1 < ND) ? fabsf(Mm[i1][p]) : -1.0f;
                    float v2 = (i2 < ND) ? fabsf(Mm[i2][p]) : -1.0f;
                    float av; int ai;
                    if (v2 > v1) { av = v2; ai = i2; } else { av = v1; ai = i1; }
                    for (int o = 16; o; o >>= 1) {
                        float oa = __shfl_xor_sync(0xffffffffu, av, o);
                        int   oi = __shfl_xor_sync(0xffffffffu, ai, o);
                        if (oa > av || (oa == av && oi < ai)) { av = oa; ai = oi; }
                    }
                    int piv = ai;
                    if (piv != p) {
                        for (int c = p + lane; c <= ND; c += 32) {
                            float t = Mm[p][c]; Mm[p][c] = Mm[piv][c]; Mm[piv][c] = t;
                        }
                    }
                }
                __syncthreads();
                // rank-1 update: warp-per-row, pivot row cached in registers
                {
                    const float ip = 1.0f / Mm[p][p];
                    const int jj0 = p + 1 + lane;
                    const int jj1 = jj0 + 32;
                    const bool v0 = (jj0 <= ND), v1 = (jj1 <= ND);
                    const float pr0 = v0 ? Mm[p][jj0] * ip : 0.0f;
                    const float pr1 = v1 ? Mm[p][jj1] * ip : 0.0f;
                    for (int i = p + 1 + wid; i < ND; i += 4) {
                        float l = Mm[i][p];
                        if (v0) Mm[i][jj0] -= l * pr0;
                        if (v1) Mm[i][jj1] -= l * pr1;
                    }
                }
                __syncthreads();
            }

            // ---- back substitution (warp 0) ----
            if (tid < 32) {
                for (int i = ND - 1; i >= 0; i--) {
                    float s = 0.0f;
                    for (int jj = i + 1 + lane; jj < ND; jj += 32)
                        s += Mm[i][jj] * xs[jj];
                    for (int o = 16; o; o >>= 1) s += __shfl_xor_sync(0xffffffffu, s, o);
                    if (lane == 0) xs[i] = (Mm[i][ND] - s) / Mm[i][i];
                    __syncwarp();
                }
            }
            __syncthreads();
            for (int i = tid; i < ND; i += BD) yn[i] -= xs[i];
            __syncthreads();
        } // newton
    } // steps

    for (int i = tid; i < ND; i += BD) out[b * ND + i] = yn[i];
}

extern "C" void kernel_launch(void* const* d_in, const int* in_sizes, int n_in,
                              void* d_out, int out_size) {
    const float* T0  = (const float*)d_in[0];
    const float* P   = (const float*)d_in[1];
    const float* Y0  = (const float*)d_in[2];
    const float* W   = (const float*)d_in[3];
    const float* nlo = (const float*)d_in[4];
    const float* nhi = (const float*)d_in[5];
    const float* Tm  = (const float*)d_in[6];
    const float* A   = (const float*)d_in[7];
    const float* Bc  = (const float*)d_in[8];
    const float* E   = (const float*)d_in[9];
    const float* nf  = (const float*)d_in[10];
    const float* nb  = (const float*)d_in[11];
    const int*   ns  = (const int*)d_in[12];
    const int B = in_sizes[0];

    prep_kernel<<<(NRX + 127) / 128, 128>>>(nf, nb);
    reactor_kernel<<<B, BD>>>(T0, P, Y0, W, nlo, nhi, Tm, A, Bc, E, ns, (float*)d_out);
}

// round 3
// speedup vs baseline: 1.8369x; 1.1453x over previous
#include <cuda_runtime.h>

#define NS   53        // species
#define ND   54        // state dim
#define NRX  325       // reactions
#define MAXF 16        // max forward-stoich nonzeros per reaction
#define MAXN 24        // max net-stoich nonzeros per reaction
#define BD   192       // threads per block
#define NW   6         // warps per block
#define MSTR 56        // padded row stride of augmented matrix
#define RGAS 8.314462618f

// ---- sparse stoichiometry tables (built per launch by prep_kernel) ----
__device__ int   g_fcnt[NRX];
__device__ short g_fidx[NRX][MAXF];
__device__ float g_fval[NRX][MAXF];
__device__ int   g_ncnt[NRX];
__device__ short g_nidx[NRX][MAXN];
__device__ float g_nval[NRX][MAXN];

__global__ void prep_kernel(const float* __restrict__ nuf,
                            const float* __restrict__ nub) {
    int j = blockIdx.x * blockDim.x + threadIdx.x;
    if (j >= NRX) return;
    int cf = 0, cn = 0;
    for (int k = 0; k < NS; k++) {
        float f = nuf[j * NS + k];
        float b = nub[j * NS + k];
        if (f != 0.0f && cf < MAXF) {
            g_fidx[j][cf] = (short)k; g_fval[j][cf] = f; cf++;
        }
        float net = b - f;
        if (net != 0.0f && cn < MAXN) {
            g_nidx[j][cn] = (short)k; g_nval[j][cn] = net; cn++;
        }
    }
    g_fcnt[j] = cf;
    g_ncnt[j] = cn;
}

__global__ __launch_bounds__(BD, 7)
void reactor_kernel(const float* __restrict__ T0,  const float* __restrict__ Pv,
                    const float* __restrict__ Y0,  const float* __restrict__ Wm,
                    const float* __restrict__ nlo, const float* __restrict__ nhi,
                    const float* __restrict__ Tmid,
                    const float* __restrict__ rA,  const float* __restrict__ rB,
                    const float* __restrict__ rE,  const int* __restrict__ nstp,
                    float* __restrict__ out) {
    // augmented Newton matrix [I - dt*J | G], col ND is RHS
    __shared__ __align__(16) float Mm[ND][MSTR];
    __shared__ float yn[ND], ycur[ND], xs[ND];
    __shared__ float Ws[NS], invW[NS], cpR[NS], hmol[NS], dcpR[NS], Ycs[NS], mY[NS];
    __shared__ float Lc[NS], gC[NS], t0a[NS], wd[NS], uu[NS], vv[NS], hQ[NS], tmp[NS];
    __shared__ float Wor[NS], sm0[NS];
    __shared__ float sT, sMT, sLnT, sIMW, sInvIMW, sRho, sInvRho;
    __shared__ float sCp, sHu, sHv, sHTw, sDcp, sRcp, sdT;

    const int tid  = threadIdx.x;
    const int lane = tid & 31;
    const int wid  = tid >> 5;
    const int b    = blockIdx.x;

    const float P = Pv[0];
    const int n_steps = nstp[0];
    const float dt = 1.0e-6f / (float)n_steps;

    for (int k = tid; k < NS; k += BD) {
        float w = Wm[k];
        Ws[k]   = w;
        invW[k] = 1.0f / w;
        yn[1 + k] = Y0[b * NS + k];
    }
    if (tid == 0) yn[0] = T0[b];
    __syncthreads();

    for (int step = 0; step < n_steps; ++step) {
        for (int i = tid; i < ND; i += BD) ycur[i] = yn[i];
        __syncthreads();

        for (int it = 0; it < 2; ++it) {
            // ---- zero accumulators (vectorized) ----
            {
                float4* M4 = (float4*)(&Mm[0][0]);
                const float4 z4 = make_float4(0.f, 0.f, 0.f, 0.f);
                for (int idx = tid; idx < ND * MSTR / 4; idx += BD) M4[idx] = z4;
            }
            for (int k = tid; k < NS; k += BD) { wd[k] = 0.0f; uu[k] = 0.0f; vv[k] = 0.0f; }
            if (tid == 0) {
                float Tr = yn[0];
                float Tc = fminf(fmaxf(Tr, 200.0f), 5000.0f);
                sT = Tc;
                sMT = (Tr > 200.0f && Tr < 5000.0f) ? 1.0f : 0.0f;
                sLnT = logf(Tc);
            }
            __syncthreads();

            const float T = sT;
            const float invT = 1.0f / T;
            // ---- per-species thermo ----
            for (int k = tid; k < NS; k += BD) {
                float Yr = yn[1 + k];
                float Yc = fminf(fmaxf(Yr, 0.0f), 1.0f);
                Ycs[k] = Yc;
                mY[k]  = (Yr > 0.0f && Yr < 1.0f) ? 1.0f : 0.0f;
                const float* a = (T < Tmid[k]) ? (nlo + 7 * k) : (nhi + 7 * k);
                float a0 = a[0], a1 = a[1], a2 = a[2], a3 = a[3], a4 = a[4], a5 = a[5];
                float T2 = T * T, T3 = T2 * T, T4 = T2 * T2;
                cpR[k]  = a0 + a1 * T + a2 * T2 + a3 * T3 + a4 * T4;
                float hRT = a0 + a1 * T * 0.5f + a2 * T2 * (1.0f / 3.0f)
                          + a3 * T3 * 0.25f + a4 * T4 * 0.2f + a5 * invT;
                hmol[k] = hRT * RGAS * T;
                dcpR[k] = a1 + 2.0f * a2 * T + 3.0f * a3 * T2 + 4.0f * a4 * T3;
                tmp[k]  = Yc * invW[k];
            }
            __syncthreads();
            if (tid < 32) {
                float s = (lane < NS ? tmp[lane] : 0.0f)
                        + (lane + 32 < NS ? tmp[lane + 32] : 0.0f);
                for (int o = 16; o; o >>= 1) s += __shfl_xor_sync(0xffffffffu, s, o);
                if (lane == 0) {
                    sIMW = s; sInvIMW = 1.0f / s;
                    float rho = P / (RGAS * T * s);
                    sRho = rho; sInvRho = (RGAS * T * s) / P;
                }
            }
            __syncthreads();
            const float rho = sRho, invRho = sInvRho, invIMW = sInvIMW;
            for (int k = tid; k < NS; k += BD) {
                float iw = invW[k];
                float C  = rho * Ycs[k] * iw;
                float Ce = C + 1e-30f;
                Lc[k]  = logf(Ce);
                gC[k]  = C / Ce;
                t0a[k] = rho * iw / Ce;
                Wor[k] = Ws[k] * invRho;
                sm0[k] = -invIMW * iw;
            }
            __syncthreads();

            // ---- reaction pass: rates + exact sensitivities ----
            const float RT = RGAS * T;
            const float invRT = 1.0f / RT;
            for (int j = tid; j < NRX; j += BD) {
                float Aj = rA[j], bj = rB[j], Ej = rE[j];
                float kf = Aj * expf(bj * sLnT - Ej * invRT);
                int nf = g_fcnt[j];
                float sL = 0.0f, Pj = 0.0f;
                for (int e = 0; e < nf; e++) {
                    int k = g_fidx[j][e]; float v = g_fval[j][e];
                    sL += v * Lc[k]; Pj += v * gC[k];
                }
                float r  = kf * expf(sL);
                float rT = (r * invT) * (bj + Ej * invRT - Pj);   // dr/dT (unmasked)
                float rP = r * Pj;
                int nn = g_ncnt[j];
                for (int e = 0; e < nn; e++) {
                    int k = g_nidx[j][e]; float nu = g_nval[j][e];
                    atomicAdd(&wd[k], nu * r);
                    atomicAdd(&uu[k], nu * rP);
                    atomicAdd(&vv[k], nu * rT);
                    float nur = nu * r;
                    for (int e2 = 0; e2 < nf; e2++)
                        atomicAdd(&Mm[k + 1][g_fidx[j][e2] + 1], nur * g_fval[j][e2]);
                }
            }
            __syncthreads();

            // ---- scalar reductions ----
            if (tid < 32) {
                float cp = 0, H = 0, hu = 0, hv = 0, hw = 0, dc = 0;
                for (int k = lane; k < NS; k += 32) {
                    float yw = Ycs[k] * invW[k];
                    cp += yw * cpR[k];
                    H  += hmol[k] * wd[k];
                    hu += hmol[k] * uu[k];
                    hv += hmol[k] * vv[k];
                    hw += cpR[k] * wd[k];
                    dc += yw * dcpR[k];
                }
                for (int o = 16; o; o >>= 1) {
                    cp += __shfl_xor_sync(0xffffffffu, cp, o);
                    H  += __shfl_xor_sync(0xffffffffu, H,  o);
                    hu += __shfl_xor_sync(0xffffffffu, hu, o);
                    hv += __shfl_xor_sync(0xffffffffu, hv, o);
                    hw += __shfl_xor_sync(0xffffffffu, hw, o);
                    dc += __shfl_xor_sync(0xffffffffu, dc, o);
                }
                if (lane == 0) {
                    float cpm = RGAS * cp;
                    sCp = cpm; sHu = hu; sHv = hv;
                    sHTw = RGAS * hw; sDcp = RGAS * dc;
                    float rcp = rho * cpm;
                    sRcp = rcp;
                    sdT = -H / rcp;
                }
            }
            __syncthreads();

            // ---- hQ_m = sum_k h_k * Qraw[k][m] (before M transform) ----
            for (int m = tid; m < NS; m += BD) {
                float s = 0.0f;
                for (int k = 0; k < NS; k++) s += hmol[k] * Mm[k + 1][m + 1];
                hQ[m] = s;
            }
            __syncthreads();

            // ---- build M = I - dt*J (warp-per-row, lane-per-col) ----
            const float rcp = sRcp, dTv = sdT, cpm = sCp, huv = sHu;
            const float invCpm = 1.0f / cpm, invRcp = 1.0f / rcp;
            for (int k = wid; k < NS; k += NW) {
                float uk  = uu[k] - wd[k];
                float wok = Wor[k];
                for (int m = lane; m < NS; m += 32) {
                    float q = Mm[k + 1][m + 1];            // Qraw_{km}
                    float J = mY[m] * wok * (uk * sm0[m] + q * t0a[m]);
                    Mm[k + 1][m + 1] = ((k == m) ? 1.0f : 0.0f) - dt * J;
                }
            }
            __syncthreads();
            for (int k = tid; k < NS; k += BD) {
                float Jk0 = sMT * Wor[k] * (vv[k] + wd[k] * invT);
                Mm[k + 1][0] = -dt * Jk0;
                float sm0k = sm0[k];
                float J0m = mY[k] * (-(huv * sm0k + hQ[k] * t0a[k]) * invRcp
                                     - dTv * (sm0k + cpR[k] * RGAS * invW[k] * invCpm));
                Mm[0][k + 1] = -dt * J0m;
                float fk = wd[k] * Wor[k];
                Mm[k + 1][ND] = yn[1 + k] - ycur[1 + k] - dt * fk;
            }
            if (tid == 0) {
                float J00 = sMT * (-(sHTw + sHv) / rcp
                                   - dTv * (-invT + sDcp / cpm));
                Mm[0][0]  = 1.0f - dt * J00;
                Mm[0][ND] = yn[0] - ycur[0] - dt * dTv;
            }
            __syncthreads();

            // ---- blocked LU (panel of 2 cols) with partial pivoting ----
            // ND is even: 27 panel rounds. Pivot choices identical to
            // unblocked partial pivoting.
            for (int p = 0; p < ND; p += 2) {
                if (tid < 32) {
                    // -- pivot search col p over rows p..ND-1 --
                    int i1 = p + lane, i2 = p + lane + 32;
                    float v1 = (i1 < ND) ? fabsf(Mm[i1][p]) : -1.0f;
                    float v2 = (i2 < ND) ? fabsf(Mm[i2][p]) : -1.0f;
                    float av; int ai;
                    if (v2 > v1) { av = v2; ai = i2; } else { av = v1; ai = i1; }
                    for (int o = 16; o; o >>= 1) {
                        float oa = __shfl_xor_sync(0xffffffffu, av, o);
                        int   oi = __shfl_xor_sync(0xffffffffu, ai, o);
                        if (oa > av || (oa == av && oi < ai)) { av = oa; ai = oi; }
                    }
                    int piv = ai;
                    if (piv != p) {
                        for (int c = p + lane; c <= ND; c += 32) {
                            float t = Mm[p][c]; Mm[p][c] = Mm[piv][c]; Mm[piv][c] = t;
                        }
                    }
                    __syncwarp();
                    // -- scale col p (store L) and update col p+1 --
                    float ip   = 1.0f / Mm[p][p];
                    float up01 = Mm[p][p + 1];
                    for (int i = p + 1 + lane; i < ND; i += 32) {
                        float l = Mm[i][p] * ip;
                        Mm[i][p] = l;
                        Mm[i][p + 1] -= l * up01;
                    }
                    __syncwarp();
                    // -- pivot search col p+1 over rows p+1..ND-1 --
                    int q = p + 1;
                    i1 = q + lane; i2 = q + lane + 32;
                    v1 = (i1 < ND) ? fabsf(Mm[i1][q]) : -1.0f;
                    v2 = (i2 < ND) ? fabsf(Mm[i2][q]) : -1.0f;
                    if (v2 > v1) { av = v2; ai = i2; } else { av = v1; ai = i1; }
                    for (int o = 16; o; o >>= 1) {
                        float oa = __shfl_xor_sync(0xffffffffu, av, o);
                        int   oi = __shfl_xor_sync(0xffffffffu, ai, o);
                        if (oa > av || (oa == av && oi < ai)) { av = oa; ai = oi; }
                    }
                    int piv2 = ai;
                    if (piv2 != q) {
                        for (int c = p + lane; c <= ND; c += 32) {   // incl. L col p
                            float t = Mm[q][c]; Mm[q][c] = Mm[piv2][c]; Mm[piv2][c] = t;
                        }
                    }
                    __syncwarp();
                    // -- scale col p+1 (rows > p+1) and finish U row p+1 --
                    float ip2 = 1.0f / Mm[q][q];
                    for (int i = q + 1 + lane; i < ND; i += 32)
                        Mm[i][q] *= ip2;
                    float lqp = Mm[q][p];                    // scaled L[p+1][p]
                    for (int jj = p + 2 + lane; jj <= ND; jj += 32)
                        Mm[q][jj] -= lqp * Mm[p][jj];
                }
                __syncthreads();
                // -- rank-2 trailing update, pivot rows cached in registers --
                {
                    const int jj0 = p + 2 + lane;
                    const int jj1 = jj0 + 32;
                    const bool c0 = (jj0 <= ND), c1 = (jj1 <= ND);
                    const float u00 = c0 ? Mm[p][jj0]     : 0.0f;
                    const float u01 = c1 ? Mm[p][jj1]     : 0.0f;
                    const float u10 = c0 ? Mm[p + 1][jj0] : 0.0f;
                    const float u11 = c1 ? Mm[p + 1][jj1] : 0.0f;
                    for (int i = p + 2 + wid; i < ND; i += NW) {
                        float l0 = Mm[i][p];
                        float l1 = Mm[i][p + 1];
                        if (c0) Mm[i][jj0] -= l0 * u00 + l1 * u10;
                        if (c1) Mm[i][jj1] -= l0 * u01 + l1 * u11;
                    }
                }
                __syncthreads();
            }

            // ---- back substitution (warp 0) ----
            if (tid < 32) {
                for (int i = ND - 1; i >= 0; i--) {
                    float s = 0.0f;
                    for (int jj = i + 1 + lane; jj < ND; jj += 32)
                        s += Mm[i][jj] * xs[jj];
                    for (int o = 16; o; o >>= 1) s += __shfl_xor_sync(0xffffffffu, s, o);
                    if (lane == 0) xs[i] = (Mm[i][ND] - s) / Mm[i][i];
                    __syncwarp();
                }
            }
            __syncthreads();
            for (int i = tid; i < ND; i += BD) yn[i] -= xs[i];
            __syncthreads();
        } // newton
    } // steps

    for (int i = tid; i < ND; i += BD) out[b * ND + i] = yn[i];
}

extern "C" void kernel_launch(void* const* d_in, const int* in_sizes, int n_in,
                              void* d_out, int out_size) {
    const float* T0  = (const float*)d_in[0];
    const float* P   = (const float*)d_in[1];
    const float* Y0  = (const float*)d_in[2];
    const float* W   = (const float*)d_in[3];
    const float* nlo = (const float*)d_in[4];
    const float* nhi = (const float*)d_in[5];
    const float* Tm  = (const float*)d_in[6];
    const float* A   = (const float*)d_in[7];
    const float* Bc  = (const float*)d_in[8];
    const float* E   = (const float*)d_in[9];
    const float* nf  = (const float*)d_in[10];
    const float* nb  = (const float*)d_in[11];
    const int*   ns  = (const int*)d_in[12];
    const int B = in_sizes[0];

    prep_kernel<<<(NRX + 127) / 128, 128>>>(nf, nb);
    reactor_kernel<<<B, BD>>>(T0, P, Y0, W, nlo, nhi, Tm, A, Bc, E, ns, (float*)d_out);
}

// round 4
// speedup vs baseline: 1.9211x; 1.0459x over previous
#include <cuda_runtime.h>

#define NS   53        // species
#define ND   54        // state dim
#define NRX  325       // reactions
#define MAXF 16        // max forward-stoich nonzeros per reaction
#define MAXN 24        // max net-stoich nonzeros per reaction
#define BD   192       // threads per block
#define NW   6         // warps per block
#define MSTR 56        // padded row stride of augmented matrix
#define RGAS 8.314462618f

// ---- sparse stoichiometry tables (built per launch by prep_kernel) ----
__device__ int   g_fcnt[NRX];
__device__ short g_fidx[NRX][MAXF];
__device__ float g_fval[NRX][MAXF];
__device__ int   g_ncnt[NRX];
__device__ short g_nidx[NRX][MAXN];
__device__ float g_nval[NRX][MAXN];

__global__ void prep_kernel(const float* __restrict__ nuf,
                            const float* __restrict__ nub) {
    int j = blockIdx.x * blockDim.x + threadIdx.x;
    if (j >= NRX) return;
    int cf = 0, cn = 0;
    for (int k = 0; k < NS; k++) {
        float f = nuf[j * NS + k];
        float b = nub[j * NS + k];
        if (f != 0.0f && cf < MAXF) {
            g_fidx[j][cf] = (short)k; g_fval[j][cf] = f; cf++;
        }
        float net = b - f;
        if (net != 0.0f && cn < MAXN) {
            g_nidx[j][cn] = (short)k; g_nval[j][cn] = net; cn++;
        }
    }
    g_fcnt[j] = cf;
    g_ncnt[j] = cn;
}

__global__ __launch_bounds__(BD, 7)
void reactor_kernel(const float* __restrict__ T0,  const float* __restrict__ Pv,
                    const float* __restrict__ Y0,  const float* __restrict__ Wm,
                    const float* __restrict__ nlo, const float* __restrict__ nhi,
                    const float* __restrict__ Tmid,
                    const float* __restrict__ rA,  const float* __restrict__ rB,
                    const float* __restrict__ rE,  const int* __restrict__ nstp,
                    float* __restrict__ out) {
    // augmented Newton matrix [I - dt*J | G], col ND is RHS, col ND+1 is pad
    __shared__ __align__(16) float Mm[ND][MSTR];
    __shared__ float yn[ND], ycur[ND], xs[ND];
    __shared__ float Ws[NS], invW[NS], cpR[NS], hmol[NS], dcpR[NS], Ycs[NS], mY[NS];
    __shared__ float Lc[NS], gC[NS], t0a[NS], wd[NS], uu[NS], vv[NS], hQ[NS], tmp[NS];
    __shared__ float Wor[NS], sm0[NS];
    __shared__ float sT, sMT, sLnT, sIMW, sInvIMW, sRho, sInvRho;
    __shared__ float sCp, sHu, sHv, sHTw, sDcp, sRcp, sdT;

    const int tid  = threadIdx.x;
    const int lane = tid & 31;
    const int wid  = tid >> 5;
    const int b    = blockIdx.x;

    const float P = Pv[0];
    const int n_steps = nstp[0];
    const float dt = 1.0e-6f / (float)n_steps;

    for (int k = tid; k < NS; k += BD) {
        float w = Wm[k];
        Ws[k]   = w;
        invW[k] = 1.0f / w;
        yn[1 + k] = Y0[b * NS + k];
    }
    if (tid == 0) yn[0] = T0[b];
    __syncthreads();

    for (int step = 0; step < n_steps; ++step) {
        for (int i = tid; i < ND; i += BD) ycur[i] = yn[i];
        __syncthreads();

        for (int it = 0; it < 2; ++it) {
            // ---- zero accumulators (vectorized) ----
            {
                float4* M4 = (float4*)(&Mm[0][0]);
                const float4 z4 = make_float4(0.f, 0.f, 0.f, 0.f);
                for (int idx = tid; idx < ND * MSTR / 4; idx += BD) M4[idx] = z4;
            }
            for (int k = tid; k < NS; k += BD) { wd[k] = 0.0f; uu[k] = 0.0f; vv[k] = 0.0f; }
            if (tid == 0) {
                float Tr = yn[0];
                float Tc = fminf(fmaxf(Tr, 200.0f), 5000.0f);
                sT = Tc;
                sMT = (Tr > 200.0f && Tr < 5000.0f) ? 1.0f : 0.0f;
                sLnT = logf(Tc);
            }
            __syncthreads();

            const float T = sT;
            const float invT = 1.0f / T;
            // ---- per-species thermo ----
            for (int k = tid; k < NS; k += BD) {
                float Yr = yn[1 + k];
                float Yc = fminf(fmaxf(Yr, 0.0f), 1.0f);
                Ycs[k] = Yc;
                mY[k]  = (Yr > 0.0f && Yr < 1.0f) ? 1.0f : 0.0f;
                const float* a = (T < Tmid[k]) ? (nlo + 7 * k) : (nhi + 7 * k);
                float a0 = a[0], a1 = a[1], a2 = a[2], a3 = a[3], a4 = a[4], a5 = a[5];
                float T2 = T * T, T3 = T2 * T, T4 = T2 * T2;
                cpR[k]  = a0 + a1 * T + a2 * T2 + a3 * T3 + a4 * T4;
                float hRT = a0 + a1 * T * 0.5f + a2 * T2 * (1.0f / 3.0f)
                          + a3 * T3 * 0.25f + a4 * T4 * 0.2f + a5 * invT;
                hmol[k] = hRT * RGAS * T;
                dcpR[k] = a1 + 2.0f * a2 * T + 3.0f * a3 * T2 + 4.0f * a4 * T3;
                tmp[k]  = Yc * invW[k];
            }
            __syncthreads();
            if (tid < 32) {
                float s = (lane < NS ? tmp[lane] : 0.0f)
                        + (lane + 32 < NS ? tmp[lane + 32] : 0.0f);
                for (int o = 16; o; o >>= 1) s += __shfl_xor_sync(0xffffffffu, s, o);
                if (lane == 0) {
                    sIMW = s; sInvIMW = 1.0f / s;
                    float rho = P / (RGAS * T * s);
                    sRho = rho; sInvRho = (RGAS * T * s) / P;
                }
            }
            __syncthreads();
            const float rho = sRho, invRho = sInvRho, invIMW = sInvIMW;
            for (int k = tid; k < NS; k += BD) {
                float iw = invW[k];
                float C  = rho * Ycs[k] * iw;
                float Ce = C + 1e-30f;
                Lc[k]  = logf(Ce);
                gC[k]  = C / Ce;
                t0a[k] = rho * iw / Ce;
                Wor[k] = Ws[k] * invRho;
                sm0[k] = -invIMW * iw;
            }
            __syncthreads();

            // ---- reaction pass: rates + exact sensitivities ----
            const float RT = RGAS * T;
            const float invRT = 1.0f / RT;
            for (int j = tid; j < NRX; j += BD) {
                float Aj = rA[j], bj = rB[j], Ej = rE[j];
                float kf = Aj * expf(bj * sLnT - Ej * invRT);
                int nf = g_fcnt[j];
                float sL = 0.0f, Pj = 0.0f;
                for (int e = 0; e < nf; e++) {
                    int k = g_fidx[j][e]; float v = g_fval[j][e];
                    sL += v * Lc[k]; Pj += v * gC[k];
                }
                float r  = kf * expf(sL);
                float rT = (r * invT) * (bj + Ej * invRT - Pj);   // dr/dT (unmasked)
                float rP = r * Pj;
                int nn = g_ncnt[j];
                for (int e = 0; e < nn; e++) {
                    int k = g_nidx[j][e]; float nu = g_nval[j][e];
                    atomicAdd(&wd[k], nu * r);
                    atomicAdd(&uu[k], nu * rP);
                    atomicAdd(&vv[k], nu * rT);
                    float nur = nu * r;
                    for (int e2 = 0; e2 < nf; e2++)
                        atomicAdd(&Mm[k + 1][g_fidx[j][e2] + 1], nur * g_fval[j][e2]);
                }
            }
            __syncthreads();

            // ---- scalar reductions ----
            if (tid < 32) {
                float cp = 0, H = 0, hu = 0, hv = 0, hw = 0, dc = 0;
                for (int k = lane; k < NS; k += 32) {
                    float yw = Ycs[k] * invW[k];
                    cp += yw * cpR[k];
                    H  += hmol[k] * wd[k];
                    hu += hmol[k] * uu[k];
                    hv += hmol[k] * vv[k];
                    hw += cpR[k] * wd[k];
                    dc += yw * dcpR[k];
                }
                for (int o = 16; o; o >>= 1) {
                    cp += __shfl_xor_sync(0xffffffffu, cp, o);
                    H  += __shfl_xor_sync(0xffffffffu, H,  o);
                    hu += __shfl_xor_sync(0xffffffffu, hu, o);
                    hv += __shfl_xor_sync(0xffffffffu, hv, o);
                    hw += __shfl_xor_sync(0xffffffffu, hw, o);
                    dc += __shfl_xor_sync(0xffffffffu, dc, o);
                }
                if (lane == 0) {
                    float cpm = RGAS * cp;
                    sCp = cpm; sHu = hu; sHv = hv;
                    sHTw = RGAS * hw; sDcp = RGAS * dc;
                    float rcp = rho * cpm;
                    sRcp = rcp;
                    sdT = -H / rcp;
                }
            }
            __syncthreads();

            // ---- hQ_m = sum_k h_k * Qraw[k][m] (before M transform) ----
            for (int m = tid; m < NS; m += BD) {
                float s = 0.0f;
                for (int k = 0; k < NS; k++) s += hmol[k] * Mm[k + 1][m + 1];
                hQ[m] = s;
            }
            __syncthreads();

            // ---- build M = I - dt*J (warp-per-row, lane-per-col) ----
            const float rcp = sRcp, dTv = sdT, cpm = sCp, huv = sHu;
            const float invCpm = 1.0f / cpm, invRcp = 1.0f / rcp;
            for (int k = wid; k < NS; k += NW) {
                float uk  = uu[k] - wd[k];
                float wok = Wor[k];
                for (int m = lane; m < NS; m += 32) {
                    float q = Mm[k + 1][m + 1];            // Qraw_{km}
                    float J = mY[m] * wok * (uk * sm0[m] + q * t0a[m]);
                    Mm[k + 1][m + 1] = ((k == m) ? 1.0f : 0.0f) - dt * J;
                }
            }
            __syncthreads();
            for (int k = tid; k < NS; k += BD) {
                float Jk0 = sMT * Wor[k] * (vv[k] + wd[k] * invT);
                Mm[k + 1][0] = -dt * Jk0;
                float sm0k = sm0[k];
                float J0m = mY[k] * (-(huv * sm0k + hQ[k] * t0a[k]) * invRcp
                                     - dTv * (sm0k + cpR[k] * RGAS * invW[k] * invCpm));
                Mm[0][k + 1] = -dt * J0m;
                float fk = wd[k] * Wor[k];
                Mm[k + 1][ND] = yn[1 + k] - ycur[1 + k] - dt * fk;
            }
            if (tid == 0) {
                float J00 = sMT * (-(sHTw + sHv) / rcp
                                   - dTv * (-invT + sDcp / cpm));
                Mm[0][0]  = 1.0f - dt * J00;
                Mm[0][ND] = yn[0] - ycur[0] - dt * dTv;
            }
            __syncthreads();

            // ---- blocked LU (rank-4 panels) with partial pivoting ----
            // ND = 54 = 13*4 + 2: 13 rank-4 panels + 1 rank-2 tail.
            for (int p = 0; p < ND; p += 4) {
                const int pw   = (ND - p >= 4) ? 4 : (ND - p);   // 4 or 2
                const int pend = p + pw;
                if (tid < 32) {
                    // -- panel factorization (left-looking within panel) --
                    #pragma unroll
                    for (int c = 0; c < 4; c++) {
                        if (c >= pw) break;
                        const int col = p + c;
                        // pivot search rows col..ND-1
                        int i1 = col + lane, i2 = col + lane + 32;
                        float v1 = (i1 < ND) ? fabsf(Mm[i1][col]) : -1.0f;
                        float v2 = (i2 < ND) ? fabsf(Mm[i2][col]) : -1.0f;
                        float av; int ai;
                        if (v2 > v1) { av = v2; ai = i2; } else { av = v1; ai = i1; }
                        for (int o = 16; o; o >>= 1) {
                            float oa = __shfl_xor_sync(0xffffffffu, av, o);
                            int   oi = __shfl_xor_sync(0xffffffffu, ai, o);
                            if (oa > av || (oa == av && oi < ai)) { av = oa; ai = oi; }
                        }
                        const int piv = ai;
                        if (piv != col) {
                            // swap rows col<->piv over cols p..ND (panel L + trailing + RHS)
                            for (int cc = p + lane; cc <= ND; cc += 32) {
                                float t = Mm[col][cc]; Mm[col][cc] = Mm[piv][cc]; Mm[piv][cc] = t;
                            }
                        }
                        __syncwarp();
                        const float ip = 1.0f / Mm[col][col];
                        const float u1 = (c + 1 < pw) ? Mm[col][p + c + 1] : 0.0f;
                        const float u2 = (c + 2 < pw) ? Mm[col][p + c + 2] : 0.0f;
                        const float u3 = (c + 3 < pw) ? Mm[col][p + c + 3] : 0.0f;
                        for (int i = col + 1 + lane; i < ND; i += 32) {
                            float l = Mm[i][col] * ip;
                            Mm[i][col] = l;
                            if (c + 1 < pw) Mm[i][p + c + 1] -= l * u1;
                            if (c + 2 < pw) Mm[i][p + c + 2] -= l * u2;
                            if (c + 3 < pw) Mm[i][p + c + 3] -= l * u3;
                        }
                        __syncwarp();
                    }
                }
                __syncthreads();
                // -- rank-pw trailing update, warp-per-row, f2 columns --
                // cols pend..ND (+pad col ND+1, zero-isolated): lane owns one f2 group
                {
                    const int ncol = ND + 1 - pend;          // incl RHS
                    const int ng   = (ncol + 1) >> 1;        // f2 groups (<=26)
                    const int jj   = pend + 2 * lane;        // even, 8B-aligned
                    float2 u0v, u1v, u2v, u3v;
                    const bool act = (lane < ng);
                    if (act) {
                        u0v = *(const float2*)&Mm[p][jj];
                        u1v = *(const float2*)&Mm[p + 1][jj];
                        if (pw > 2) {
                            u2v = *(const float2*)&Mm[p + 2][jj];
                            u3v = *(const float2*)&Mm[p + 3][jj];
                        }
                    }
                    for (int i = pend + wid; i < ND; i += NW) {
                        // 4 contiguous L values (cols p..p+3; tail reads junk cols safely)
                        float4 lv = *(const float4*)&Mm[i][p];
                        if (act) {
                            float2 m = *(float2*)&Mm[i][jj];
                            float ax = lv.x * u0v.x + lv.y * u1v.x;
                            float ay = lv.x * u0v.y + lv.y * u1v.y;
                            if (pw > 2) {
                                ax += lv.z * u2v.x + lv.w * u3v.x;
                                ay += lv.z * u2v.y + lv.w * u3v.y;
                            }
                            m.x -= ax; m.y -= ay;
                            *(float2*)&Mm[i][jj] = m;
                        }
                    }
                }
                __syncthreads();
            }

            // ---- back substitution (warp 0) ----
            if (tid < 32) {
                for (int i = ND - 1; i >= 0; i--) {
                    float s = 0.0f;
                    for (int jj = i + 1 + lane; jj < ND; jj += 32)
                        s += Mm[i][jj] * xs[jj];
                    for (int o = 16; o; o >>= 1) s += __shfl_xor_sync(0xffffffffu, s, o);
                    if (lane == 0) xs[i] = (Mm[i][ND] - s) / Mm[i][i];
                    __syncwarp();
                }
            }
            __syncthreads();
            for (int i = tid; i < ND; i += BD) yn[i] -= xs[i];
            __syncthreads();
        } // newton
    } // steps

    for (int i = tid; i < ND; i += BD) out[b * ND + i] = yn[i];
}

extern "C" void kernel_launch(void* const* d_in, const int* in_sizes, int n_in,
                              void* d_out, int out_size) {
    const float* T0  = (const float*)d_in[0];
    const float* P   = (const float*)d_in[1];
    const float* Y0  = (const float*)d_in[2];
    const float* W   = (const float*)d_in[3];
    const float* nlo = (const float*)d_in[4];
    const float* nhi = (const float*)d_in[5];
    const float* Tm  = (const float*)d_in[6];
    const float* A   = (const float*)d_in[7];
    const float* Bc  = (const float*)d_in[8];
    const float* E   = (const float*)d_in[9];
    const float* nf  = (const float*)d_in[10];
    const float* nb  = (const float*)d_in[11];
    const int*   ns  = (const int*)d_in[12];
    const int B = in_sizes[0];

    prep_kernel<<<(NRX + 127) / 128, 128>>>(nf, nb);
    reactor_kernel<<<B, BD>>>(T0, P, Y0, W, nlo, nhi, Tm, A, Bc, E, ns, (float*)d_out);
}

// round 5
// speedup vs baseline: 2.2505x; 1.1715x over previous
#include <cuda_runtime.h>

#define NS   53        // species
#define ND   54        // state dim
#define NRX  325       // reactions
#define MAXF 16        // max forward-stoich nonzeros per reaction
#define MAXN 24        // max net-stoich nonzeros per reaction
#define BD   192       // threads per block
#define NW   6         // warps per block
#define MSTR 56        // padded row stride of augmented matrix
#define RGAS 8.314462618f

// ---- sparse stoichiometry tables (built per launch by prep_kernel) ----
__device__ int   g_fcnt[NRX];
__device__ short g_fidx[NRX][MAXF];
__device__ float g_fval[NRX][MAXF];
__device__ int   g_ncnt[NRX];
__device__ short g_nidx[NRX][MAXN];
__device__ float g_nval[NRX][MAXN];

__global__ void prep_kernel(const float* __restrict__ nuf,
                            const float* __restrict__ nub) {
    int j = blockIdx.x * blockDim.x + threadIdx.x;
    if (j >= NRX) return;
    int cf = 0, cn = 0;
    for (int k = 0; k < NS; k++) {
        float f = nuf[j * NS + k];
        float b = nub[j * NS + k];
        if (f != 0.0f && cf < MAXF) {
            g_fidx[j][cf] = (short)k; g_fval[j][cf] = f; cf++;
        }
        float net = b - f;
        if (net != 0.0f && cn < MAXN) {
            g_nidx[j][cn] = (short)k; g_nval[j][cn] = net; cn++;
        }
    }
    g_fcnt[j] = cf;
    g_ncnt[j] = cn;
}

__global__ __launch_bounds__(BD, 7)
void reactor_kernel(const float* __restrict__ T0,  const float* __restrict__ Pv,
                    const float* __restrict__ Y0,  const float* __restrict__ Wm,
                    const float* __restrict__ nlo, const float* __restrict__ nhi,
                    const float* __restrict__ Tmid,
                    const float* __restrict__ rA,  const float* __restrict__ rB,
                    const float* __restrict__ rE,  const int* __restrict__ nstp,
                    float* __restrict__ out) {
    // augmented Newton matrix [I - dt*J | G], col ND is RHS, col ND+1 is pad
    __shared__ __align__(16) float Mm[ND][MSTR];
    __shared__ float yn[ND], ycur[ND], xs[ND];
    __shared__ float Ws[NS], invW[NS], cpR[NS], hmol[NS], dcpR[NS], Ycs[NS], mY[NS];
    __shared__ float Lc[NS], gC[NS], t0a[NS], wd[NS], uu[NS], vv[NS], hQ[NS], tmp[NS];
    __shared__ float Wor[NS], sm0[NS];
    __shared__ float sT, sMT, sLnT, sIMW, sInvIMW, sRho, sInvRho;
    __shared__ float sCp, sHu, sHv, sHTw, sDcp, sRcp, sdT;

    const int tid  = threadIdx.x;
    const int lane = tid & 31;
    const int wid  = tid >> 5;
    const int b    = blockIdx.x;

    const float P = Pv[0];
    const int n_steps = nstp[0];
    const float dt = 1.0e-6f / (float)n_steps;

    for (int k = tid; k < NS; k += BD) {
        float w = Wm[k];
        Ws[k]   = w;
        invW[k] = 1.0f / w;
        yn[1 + k] = Y0[b * NS + k];
    }
    if (tid == 0) yn[0] = T0[b];
    __syncthreads();

    for (int step = 0; step < n_steps; ++step) {
        for (int i = tid; i < ND; i += BD) ycur[i] = yn[i];
        __syncthreads();

        for (int it = 0; it < 2; ++it) {
            // ---- zero accumulators (vectorized) ----
            {
                float4* M4 = (float4*)(&Mm[0][0]);
                const float4 z4 = make_float4(0.f, 0.f, 0.f, 0.f);
                for (int idx = tid; idx < ND * MSTR / 4; idx += BD) M4[idx] = z4;
            }
            for (int k = tid; k < NS; k += BD) { wd[k] = 0.0f; uu[k] = 0.0f; vv[k] = 0.0f; }
            if (tid == 0) {
                float Tr = yn[0];
                float Tc = fminf(fmaxf(Tr, 200.0f), 5000.0f);
                sT = Tc;
                sMT = (Tr > 200.0f && Tr < 5000.0f) ? 1.0f : 0.0f;
                sLnT = logf(Tc);
            }
            __syncthreads();

            const float T = sT;
            const float invT = 1.0f / T;
            // ---- per-species thermo ----
            for (int k = tid; k < NS; k += BD) {
                float Yr = yn[1 + k];
                float Yc = fminf(fmaxf(Yr, 0.0f), 1.0f);
                Ycs[k] = Yc;
                mY[k]  = (Yr > 0.0f && Yr < 1.0f) ? 1.0f : 0.0f;
                const float* a = (T < Tmid[k]) ? (nlo + 7 * k) : (nhi + 7 * k);
                float a0 = a[0], a1 = a[1], a2 = a[2], a3 = a[3], a4 = a[4], a5 = a[5];
                float T2 = T * T, T3 = T2 * T, T4 = T2 * T2;
                cpR[k]  = a0 + a1 * T + a2 * T2 + a3 * T3 + a4 * T4;
                float hRT = a0 + a1 * T * 0.5f + a2 * T2 * (1.0f / 3.0f)
                          + a3 * T3 * 0.25f + a4 * T4 * 0.2f + a5 * invT;
                hmol[k] = hRT * RGAS * T;
                dcpR[k] = a1 + 2.0f * a2 * T + 3.0f * a3 * T2 + 4.0f * a4 * T3;
                tmp[k]  = Yc * invW[k];
            }
            __syncthreads();
            if (tid < 32) {
                float s = (lane < NS ? tmp[lane] : 0.0f)
                        + (lane + 32 < NS ? tmp[lane + 32] : 0.0f);
                for (int o = 16; o; o >>= 1) s += __shfl_xor_sync(0xffffffffu, s, o);
                if (lane == 0) {
                    sIMW = s; sInvIMW = 1.0f / s;
                    float rho = P / (RGAS * T * s);
                    sRho = rho; sInvRho = (RGAS * T * s) / P;
                }
            }
            __syncthreads();
            const float rho = sRho, invRho = sInvRho, invIMW = sInvIMW;
            for (int k = tid; k < NS; k += BD) {
                float iw = invW[k];
                float C  = rho * Ycs[k] * iw;
                float Ce = C + 1e-30f;
                Lc[k]  = logf(Ce);
                gC[k]  = C / Ce;
                t0a[k] = rho * iw / Ce;
                Wor[k] = Ws[k] * invRho;
                sm0[k] = -invIMW * iw;
            }
            __syncthreads();

            // ---- reaction pass: rates + exact sensitivities ----
            const float RT = RGAS * T;
            const float invRT = 1.0f / RT;
            for (int j = tid; j < NRX; j += BD) {
                float Aj = rA[j], bj = rB[j], Ej = rE[j];
                float kf = Aj * expf(bj * sLnT - Ej * invRT);
                int nf = g_fcnt[j];
                float sL = 0.0f, Pj = 0.0f;
                for (int e = 0; e < nf; e++) {
                    int k = g_fidx[j][e]; float v = g_fval[j][e];
                    sL += v * Lc[k]; Pj += v * gC[k];
                }
                float r  = kf * expf(sL);
                float rT = (r * invT) * (bj + Ej * invRT - Pj);   // dr/dT (unmasked)
                float rP = r * Pj;
                int nn = g_ncnt[j];
                for (int e = 0; e < nn; e++) {
                    int k = g_nidx[j][e]; float nu = g_nval[j][e];
                    atomicAdd(&wd[k], nu * r);
                    atomicAdd(&uu[k], nu * rP);
                    atomicAdd(&vv[k], nu * rT);
                    float nur = nu * r;
                    for (int e2 = 0; e2 < nf; e2++)
                        atomicAdd(&Mm[k + 1][g_fidx[j][e2] + 1], nur * g_fval[j][e2]);
                }
            }
            __syncthreads();

            // ---- scalar reductions ----
            if (tid < 32) {
                float cp = 0, H = 0, hu = 0, hv = 0, hw = 0, dc = 0;
                for (int k = lane; k < NS; k += 32) {
                    float yw = Ycs[k] * invW[k];
                    cp += yw * cpR[k];
                    H  += hmol[k] * wd[k];
                    hu += hmol[k] * uu[k];
                    hv += hmol[k] * vv[k];
                    hw += cpR[k] * wd[k];
                    dc += yw * dcpR[k];
                }
                for (int o = 16; o; o >>= 1) {
                    cp += __shfl_xor_sync(0xffffffffu, cp, o);
                    H  += __shfl_xor_sync(0xffffffffu, H,  o);
                    hu += __shfl_xor_sync(0xffffffffu, hu, o);
                    hv += __shfl_xor_sync(0xffffffffu, hv, o);
                    hw += __shfl_xor_sync(0xffffffffu, hw, o);
                    dc += __shfl_xor_sync(0xffffffffu, dc, o);
                }
                if (lane == 0) {
                    float cpm = RGAS * cp;
                    sCp = cpm; sHu = hu; sHv = hv;
                    sHTw = RGAS * hw; sDcp = RGAS * dc;
                    float rcp = rho * cpm;
                    sRcp = rcp;
                    sdT = -H / rcp;
                }
            }
            __syncthreads();

            // ---- hQ_m = sum_k h_k * Qraw[k][m] (before M transform) ----
            for (int m = tid; m < NS; m += BD) {
                float s = 0.0f;
                for (int k = 0; k < NS; k++) s += hmol[k] * Mm[k + 1][m + 1];
                hQ[m] = s;
            }
            __syncthreads();

            // ---- build M = I - dt*J (warp-per-row, lane-per-col) ----
            const float rcp = sRcp, dTv = sdT, cpm = sCp, huv = sHu;
            const float invCpm = 1.0f / cpm, invRcp = 1.0f / rcp;
            for (int k = wid; k < NS; k += NW) {
                float uk  = uu[k] - wd[k];
                float wok = Wor[k];
                for (int m = lane; m < NS; m += 32) {
                    float q = Mm[k + 1][m + 1];            // Qraw_{km}
                    float J = mY[m] * wok * (uk * sm0[m] + q * t0a[m]);
                    Mm[k + 1][m + 1] = ((k == m) ? 1.0f : 0.0f) - dt * J;
                }
            }
            __syncthreads();
            for (int k = tid; k < NS; k += BD) {
                float Jk0 = sMT * Wor[k] * (vv[k] + wd[k] * invT);
                Mm[k + 1][0] = -dt * Jk0;
                float sm0k = sm0[k];
                float J0m = mY[k] * (-(huv * sm0k + hQ[k] * t0a[k]) * invRcp
                                     - dTv * (sm0k + cpR[k] * RGAS * invW[k] * invCpm));
                Mm[0][k + 1] = -dt * J0m;
                float fk = wd[k] * Wor[k];
                Mm[k + 1][ND] = yn[1 + k] - ycur[1 + k] - dt * fk;
            }
            if (tid == 0) {
                float J00 = sMT * (-(sHTw + sHv) / rcp
                                   - dTv * (-invT + sDcp / cpm));
                Mm[0][0]  = 1.0f - dt * J00;
                Mm[0][ND] = yn[0] - ycur[0] - dt * dTv;
            }
            __syncthreads();

            // ---- blocked LU (rank-4 panels), NO pivoting ----
            // ND = 54 = 13*4 + 2: 13 rank-4 panels + 1 rank-2 tail.
            for (int p = 0; p < ND; p += 4) {
                const int pw   = (ND - p >= 4) ? 4 : (ND - p);   // 4 or 2
                const int pend = p + pw;
                if (tid < 32) {
                    // -- panel factorization (no search, no swaps) --
                    #pragma unroll
                    for (int c = 0; c < 4; c++) {
                        if (c >= pw) break;
                        const int col = p + c;
                        const float ip = 1.0f / Mm[col][col];
                        const float u1 = (c + 1 < pw) ? Mm[col][p + c + 1] : 0.0f;
                        const float u2 = (c + 2 < pw) ? Mm[col][p + c + 2] : 0.0f;
                        const float u3 = (c + 3 < pw) ? Mm[col][p + c + 3] : 0.0f;
                        for (int i = col + 1 + lane; i < ND; i += 32) {
                            float l = Mm[i][col] * ip;
                            Mm[i][col] = l;
                            if (c + 1 < pw) Mm[i][p + c + 1] -= l * u1;
                            if (c + 2 < pw) Mm[i][p + c + 2] -= l * u2;
                            if (c + 3 < pw) Mm[i][p + c + 3] -= l * u3;
                        }
                        __syncwarp();
                    }
                }
                __syncthreads();
                // -- rank-pw trailing update, warp-per-row, f2 columns --
                {
                    const int ncol = ND + 1 - pend;          // incl RHS
                    const int ng   = (ncol + 1) >> 1;        // f2 groups (<=26)
                    const int jj   = pend + 2 * lane;        // even, 8B-aligned
                    float2 u0v, u1v, u2v, u3v;
                    const bool act = (lane < ng);
                    if (act) {
                        u0v = *(const float2*)&Mm[p][jj];
                        u1v = *(const float2*)&Mm[p + 1][jj];
                        if (pw > 2) {
                            u2v = *(const float2*)&Mm[p + 2][jj];
                            u3v = *(const float2*)&Mm[p + 3][jj];
                        }
                    }
                    for (int i = pend + wid; i < ND; i += NW) {
                        float4 lv = *(const float4*)&Mm[i][p];
                        if (act) {
                            float2 m = *(float2*)&Mm[i][jj];
                            float ax = lv.x * u0v.x + lv.y * u1v.x;
                            float ay = lv.x * u0v.y + lv.y * u1v.y;
                            if (pw > 2) {
                                ax += lv.z * u2v.x + lv.w * u3v.x;
                                ay += lv.z * u2v.y + lv.w * u3v.y;
                            }
                            m.x -= ax; m.y -= ay;
                            *(float2*)&Mm[i][jj] = m;
                        }
                    }
                }
                __syncthreads();
            }

            // ---- back substitution (warp 0) ----
            if (tid < 32) {
                for (int i = ND - 1; i >= 0; i--) {
                    float s = 0.0f;
                    for (int jj = i + 1 + lane; jj < ND; jj += 32)
                        s += Mm[i][jj] * xs[jj];
                    for (int o = 16; o; o >>= 1) s += __shfl_xor_sync(0xffffffffu, s, o);
                    if (lane == 0) xs[i] = (Mm[i][ND] - s) / Mm[i][i];
                    __syncwarp();
                }
            }
            __syncthreads();
            for (int i = tid; i < ND; i += BD) yn[i] -= xs[i];
            __syncthreads();
        } // newton
    } // steps

    for (int i = tid; i < ND; i += BD) out[b * ND + i] = yn[i];
}

extern "C" void kernel_launch(void* const* d_in, const int* in_sizes, int n_in,
                              void* d_out, int out_size) {
    const float* T0  = (const float*)d_in[0];
    const float* P   = (const float*)d_in[1];
    const float* Y0  = (const float*)d_in[2];
    const float* W   = (const float*)d_in[3];
    const float* nlo = (const float*)d_in[4];
    const float* nhi = (const float*)d_in[5];
    const float* Tm  = (const float*)d_in[6];
    const float* A   = (const float*)d_in[7];
    const float* Bc  = (const float*)d_in[8];
    const float* E   = (const float*)d_in[9];
    const float* nf  = (const float*)d_in[10];
    const float* nb  = (const float*)d_in[11];
    const int*   ns  = (const int*)d_in[12];
    const int B = in_sizes[0];

    prep_kernel<<<(NRX + 127) / 128, 128>>>(nf, nb);
    reactor_kernel<<<B, BD>>>(T0, P, Y0, W, nlo, nhi, Tm, A, Bc, E, ns, (float*)d_out);
}

// round 6
// speedup vs baseline: 3.2415x; 1.4403x over previous
#include <cuda_runtime.h>

#define NS   53        // species
#define ND   54        // state dim
#define NRX  325       // reactions
#define MAXF 16        // max forward-stoich nonzeros per reaction
#define MAXN 24        // max net-stoich nonzeros per reaction
#define BD   192       // threads per block
#define NW   6         // warps per block
#define MSTR 56        // padded row stride of matrix
#define KRICH 6        // Richardson iterations (error ~ ||dtJ||^7)
#define RGAS 8.314462618f

// ---- sparse stoichiometry tables (built per launch by prep_kernel) ----
__device__ int   g_fcnt[NRX];
__device__ short g_fidx[NRX][MAXF];
__device__ float g_fval[NRX][MAXF];
__device__ int   g_ncnt[NRX];
__device__ short g_nidx[NRX][MAXN];
__device__ float g_nval[NRX][MAXN];

__global__ void prep_kernel(const float* __restrict__ nuf,
                            const float* __restrict__ nub) {
    int j = blockIdx.x * blockDim.x + threadIdx.x;
    if (j >= NRX) return;
    int cf = 0, cn = 0;
    for (int k = 0; k < NS; k++) {
        float f = nuf[j * NS + k];
        float b = nub[j * NS + k];
        if (f != 0.0f && cf < MAXF) {
            g_fidx[j][cf] = (short)k; g_fval[j][cf] = f; cf++;
        }
        float net = b - f;
        if (net != 0.0f && cn < MAXN) {
            g_nidx[j][cn] = (short)k; g_nval[j][cn] = net; cn++;
        }
    }
    g_fcnt[j] = cf;
    g_ncnt[j] = cn;
}

__global__ __launch_bounds__(BD, 7)
void reactor_kernel(const float* __restrict__ T0,  const float* __restrict__ Pv,
                    const float* __restrict__ Y0,  const float* __restrict__ Wm,
                    const float* __restrict__ nlo, const float* __restrict__ nhi,
                    const float* __restrict__ Tmid,
                    const float* __restrict__ rA,  const float* __restrict__ rB,
                    const float* __restrict__ rE,  const int* __restrict__ nstp,
                    float* __restrict__ out) {
    // Mm holds P = dt*J (54x54); solve (I-P)x = G by x <- G + P x
    __shared__ __align__(16) float Mm[ND][MSTR];
    __shared__ float yn[ND], ycur[ND], gg[ND], xsA[ND], xsB[ND];
    __shared__ float Ws[NS], invW[NS], cpR[NS], hmol[NS], dcpR[NS], Ycs[NS], mY[NS];
    __shared__ float Lc[NS], gC[NS], t0a[NS], wd[NS], uu[NS], vv[NS], hQ[NS], tmp[NS];
    __shared__ float Wor[NS], sm0[NS];
    __shared__ float sT, sMT, sLnT, sIMW, sInvIMW, sRho, sInvRho;
    __shared__ float sCp, sHu, sHv, sHTw, sDcp, sRcp, sdT;

    const int tid  = threadIdx.x;
    const int lane = tid & 31;
    const int wid  = tid >> 5;
    const int b    = blockIdx.x;

    const float P = Pv[0];
    const int n_steps = nstp[0];
    const float dt = 1.0e-6f / (float)n_steps;

    for (int k = tid; k < NS; k += BD) {
        float w = Wm[k];
        Ws[k]   = w;
        invW[k] = 1.0f / w;
        yn[1 + k] = Y0[b * NS + k];
    }
    if (tid == 0) yn[0] = T0[b];
    __syncthreads();

    for (int step = 0; step < n_steps; ++step) {
        for (int i = tid; i < ND; i += BD) ycur[i] = yn[i];
        __syncthreads();

        for (int it = 0; it < 2; ++it) {
            // ---- zero accumulators (vectorized) ----
            {
                float4* M4 = (float4*)(&Mm[0][0]);
                const float4 z4 = make_float4(0.f, 0.f, 0.f, 0.f);
                for (int idx = tid; idx < ND * MSTR / 4; idx += BD) M4[idx] = z4;
            }
            for (int k = tid; k < NS; k += BD) { wd[k] = 0.0f; uu[k] = 0.0f; vv[k] = 0.0f; }
            if (tid == 0) {
                float Tr = yn[0];
                float Tc = fminf(fmaxf(Tr, 200.0f), 5000.0f);
                sT = Tc;
                sMT = (Tr > 200.0f && Tr < 5000.0f) ? 1.0f : 0.0f;
                sLnT = logf(Tc);
            }
            __syncthreads();

            const float T = sT;
            const float invT = 1.0f / T;
            // ---- per-species thermo ----
            for (int k = tid; k < NS; k += BD) {
                float Yr = yn[1 + k];
                float Yc = fminf(fmaxf(Yr, 0.0f), 1.0f);
                Ycs[k] = Yc;
                mY[k]  = (Yr > 0.0f && Yr < 1.0f) ? 1.0f : 0.0f;
                const float* a = (T < Tmid[k]) ? (nlo + 7 * k) : (nhi + 7 * k);
                float a0 = a[0], a1 = a[1], a2 = a[2], a3 = a[3], a4 = a[4], a5 = a[5];
                float T2 = T * T, T3 = T2 * T, T4 = T2 * T2;
                cpR[k]  = a0 + a1 * T + a2 * T2 + a3 * T3 + a4 * T4;
                float hRT = a0 + a1 * T * 0.5f + a2 * T2 * (1.0f / 3.0f)
                          + a3 * T3 * 0.25f + a4 * T4 * 0.2f + a5 * invT;
                hmol[k] = hRT * RGAS * T;
                dcpR[k] = a1 + 2.0f * a2 * T + 3.0f * a3 * T2 + 4.0f * a4 * T3;
                tmp[k]  = Yc * invW[k];
            }
            __syncthreads();
            if (tid < 32) {
                float s = (lane < NS ? tmp[lane] : 0.0f)
                        + (lane + 32 < NS ? tmp[lane + 32] : 0.0f);
                for (int o = 16; o; o >>= 1) s += __shfl_xor_sync(0xffffffffu, s, o);
                if (lane == 0) {
                    sIMW = s; sInvIMW = 1.0f / s;
                    float rho = P / (RGAS * T * s);
                    sRho = rho; sInvRho = (RGAS * T * s) / P;
                }
            }
            __syncthreads();
            const float rho = sRho, invRho = sInvRho, invIMW = sInvIMW;
            for (int k = tid; k < NS; k += BD) {
                float iw = invW[k];
                float C  = rho * Ycs[k] * iw;
                float Ce = C + 1e-30f;
                Lc[k]  = logf(Ce);
                gC[k]  = C / Ce;
                t0a[k] = rho * iw / Ce;
                Wor[k] = Ws[k] * invRho;
                sm0[k] = -invIMW * iw;
            }
            __syncthreads();

            // ---- reaction pass: rates + exact sensitivities ----
            const float RT = RGAS * T;
            const float invRT = 1.0f / RT;
            for (int j = tid; j < NRX; j += BD) {
                float Aj = rA[j], bj = rB[j], Ej = rE[j];
                float kf = Aj * expf(bj * sLnT - Ej * invRT);
                int nf = g_fcnt[j];
                float sL = 0.0f, Pj = 0.0f;
                for (int e = 0; e < nf; e++) {
                    int k = g_fidx[j][e]; float v = g_fval[j][e];
                    sL += v * Lc[k]; Pj += v * gC[k];
                }
                float r  = kf * expf(sL);
                float rT = (r * invT) * (bj + Ej * invRT - Pj);   // dr/dT (unmasked)
                float rP = r * Pj;
                int nn = g_ncnt[j];
                for (int e = 0; e < nn; e++) {
                    int k = g_nidx[j][e]; float nu = g_nval[j][e];
                    atomicAdd(&wd[k], nu * r);
                    atomicAdd(&uu[k], nu * rP);
                    atomicAdd(&vv[k], nu * rT);
                    float nur = nu * r;
                    for (int e2 = 0; e2 < nf; e2++)
                        atomicAdd(&Mm[k + 1][g_fidx[j][e2] + 1], nur * g_fval[j][e2]);
                }
            }
            __syncthreads();

            // ---- scalar reductions ----
            if (tid < 32) {
                float cp = 0, H = 0, hu = 0, hv = 0, hw = 0, dc = 0;
                for (int k = lane; k < NS; k += 32) {
                    float yw = Ycs[k] * invW[k];
                    cp += yw * cpR[k];
                    H  += hmol[k] * wd[k];
                    hu += hmol[k] * uu[k];
                    hv += hmol[k] * vv[k];
                    hw += cpR[k] * wd[k];
                    dc += yw * dcpR[k];
                }
                for (int o = 16; o; o >>= 1) {
                    cp += __shfl_xor_sync(0xffffffffu, cp, o);
                    H  += __shfl_xor_sync(0xffffffffu, H,  o);
                    hu += __shfl_xor_sync(0xffffffffu, hu, o);
                    hv += __shfl_xor_sync(0xffffffffu, hv, o);
                    hw += __shfl_xor_sync(0xffffffffu, hw, o);
                    dc += __shfl_xor_sync(0xffffffffu, dc, o);
                }
                if (lane == 0) {
                    float cpm = RGAS * cp;
                    sCp = cpm; sHu = hu; sHv = hv;
                    sHTw = RGAS * hw; sDcp = RGAS * dc;
                    float rcp = rho * cpm;
                    sRcp = rcp;
                    sdT = -H / rcp;
                }
            }
            __syncthreads();

            // ---- hQ_m = sum_k h_k * Qraw[k][m] (before transform) ----
            for (int m = tid; m < NS; m += BD) {
                float s = 0.0f;
                for (int k = 0; k < NS; k++) s += hmol[k] * Mm[k + 1][m + 1];
                hQ[m] = s;
            }
            __syncthreads();

            // ---- build P = dt*J (warp-per-row) and RHS G ----
            const float rcp = sRcp, dTv = sdT, cpm = sCp, huv = sHu;
            const float invCpm = 1.0f / cpm, invRcp = 1.0f / rcp;
            for (int k = wid; k < NS; k += NW) {
                float uk  = uu[k] - wd[k];
                float wok = Wor[k];
                for (int m = lane; m < NS; m += 32) {
                    float q = Mm[k + 1][m + 1];            // Qraw_{km}
                    float J = mY[m] * wok * (uk * sm0[m] + q * t0a[m]);
                    Mm[k + 1][m + 1] = dt * J;
                }
            }
            __syncthreads();
            for (int k = tid; k < NS; k += BD) {
                float Jk0 = sMT * Wor[k] * (vv[k] + wd[k] * invT);
                Mm[k + 1][0] = dt * Jk0;
                float sm0k = sm0[k];
                float J0m = mY[k] * (-(huv * sm0k + hQ[k] * t0a[k]) * invRcp
                                     - dTv * (sm0k + cpR[k] * RGAS * invW[k] * invCpm));
                Mm[0][k + 1] = dt * J0m;
                float fk = wd[k] * Wor[k];
                float g  = yn[1 + k] - ycur[1 + k] - dt * fk;
                gg[1 + k]  = g;
                xsA[1 + k] = g;
            }
            if (tid == 0) {
                float J00 = sMT * (-(sHTw + sHv) / rcp
                                   - dTv * (-invT + sDcp / cpm));
                Mm[0][0] = dt * J00;
                float g0 = yn[0] - ycur[0] - dt * dTv;
                gg[0]  = g0;
                xsA[0] = g0;
            }
            __syncthreads();

            // ---- Richardson solve: x <- G + P x   (KRICH sweeps) ----
            // warp-per-row: 54 rows / 6 warps = 9 rows each, lanes over cols
            #pragma unroll
            for (int m = 0; m < KRICH; m++) {
                const float* xin = (m & 1) ? xsB : xsA;
                float*       xout = (m & 1) ? xsA : xsB;
                const float x0 = xin[lane];
                const float x1 = (lane + 32 < ND) ? xin[lane + 32] : 0.0f;
                for (int r = wid; r < ND; r += NW) {
                    float s = Mm[r][lane] * x0;
                    if (lane + 32 < ND) s += Mm[r][lane + 32] * x1;
                    for (int o = 16; o; o >>= 1) s += __shfl_xor_sync(0xffffffffu, s, o);
                    if (lane == 0) xout[r] = gg[r] + s;
                }
                __syncthreads();
            }
            // KRICH even -> final x in xsA
            for (int i = tid; i < ND; i += BD) yn[i] -= xsA[i];
            __syncthreads();
        } // newton
    } // steps

    for (int i = tid; i < ND; i += BD) out[b * ND + i] = yn[i];
}

extern "C" void kernel_launch(void* const* d_in, const int* in_sizes, int n_in,
                              void* d_out, int out_size) {
    const float* T0  = (const float*)d_in[0];
    const float* P   = (const float*)d_in[1];
    const float* Y0  = (const float*)d_in[2];
    const float* W   = (const float*)d_in[3];
    const float* nlo = (const float*)d_in[4];
    const float* nhi = (const float*)d_in[5];
    const float* Tm  = (const float*)d_in[6];
    const float* A   = (const float*)d_in[7];
    const float* Bc  = (const float*)d_in[8];
    const float* E   = (const float*)d_in[9];
    const float* nf  = (const float*)d_in[10];
    const float* nb  = (const float*)d_in[11];
    const int*   ns  = (const int*)d_in[12];
    const int B = in_sizes[0];

    prep_kernel<<<(NRX + 127) / 128, 128>>>(nf, nb);
    reactor_kernel<<<B, BD>>>(T0, P, Y0, W, nlo, nhi, Tm, A, Bc, E, ns, (float*)d_out);
}

// round 7
// speedup vs baseline: 3.7344x; 1.1521x over previous
#include <cuda_runtime.h>

#define NS   53        // species
#define ND   54        // state dim
#define NRX  325       // reactions
#define MAXF 16        // max forward-stoich nonzeros per reaction
#define MAXN 24        // max net-stoich nonzeros per reaction
#define BD   192       // threads per block
#define NW   6         // warps per block
#define MSTR 55        // ODD row stride: column access conflict-free (gcd(55,32)=1)
#define KRICH 6        // Richardson iterations (error ~ ||dtJ||^7)
#define RGAS 8.314462618f

// ---- sparse stoichiometry tables (built per launch by prep_kernel) ----
__device__ int   g_fcnt[NRX];
__device__ short g_fidx[NRX][MAXF];
__device__ float g_fval[NRX][MAXF];
__device__ int   g_ncnt[NRX];
__device__ short g_nidx[NRX][MAXN];
__device__ float g_nval[NRX][MAXN];

__global__ void prep_kernel(const float* __restrict__ nuf,
                            const float* __restrict__ nub) {
    int j = blockIdx.x * blockDim.x + threadIdx.x;
    if (j >= NRX) return;
    int cf = 0, cn = 0;
    for (int k = 0; k < NS; k++) {
        float f = nuf[j * NS + k];
        float b = nub[j * NS + k];
        if (f != 0.0f && cf < MAXF) {
            g_fidx[j][cf] = (short)k; g_fval[j][cf] = f; cf++;
        }
        float net = b - f;
        if (net != 0.0f && cn < MAXN) {
            g_nidx[j][cn] = (short)k; g_nval[j][cn] = net; cn++;
        }
    }
    g_fcnt[j] = cf;
    g_ncnt[j] = cn;
}

__global__ __launch_bounds__(BD, 7)
void reactor_kernel(const float* __restrict__ T0,  const float* __restrict__ Pv,
                    const float* __restrict__ Y0,  const float* __restrict__ Wm,
                    const float* __restrict__ nlo, const float* __restrict__ nhi,
                    const float* __restrict__ Tmid,
                    const float* __restrict__ rA,  const float* __restrict__ rB,
                    const float* __restrict__ rE,  const int* __restrict__ nstp,
                    float* __restrict__ out) {
    // Mm holds P = dt*J (54x54); solve (I-P)x = G by x <- G + P x
    __shared__ float Mm[ND][MSTR];
    __shared__ float yn[ND], ycur[ND], gg[ND], xsA[ND], xsB[ND];
    __shared__ float Ws[NS], invW[NS], cpR[NS], hmol[NS], dcpR[NS], Ycs[NS], mY[NS];
    __shared__ float Lc[NS], gC[NS], t0a[NS], wd[NS], uu[NS], vv[NS], hQ[NS], tmp[NS];
    __shared__ float Wor[NS], sm0[NS];
    __shared__ float sT, sMT, sLnT, sIMW, sInvIMW, sRho, sInvRho;
    __shared__ float sCp, sHu, sHv, sHTw, sDcp, sRcp, sdT;

    const int tid  = threadIdx.x;
    const int lane = tid & 31;
    const int wid  = tid >> 5;
    const int b    = blockIdx.x;

    const float P = Pv[0];
    const int n_steps = nstp[0];
    const float dt = 1.0e-6f / (float)n_steps;

    for (int k = tid; k < NS; k += BD) {
        float w = Wm[k];
        Ws[k]   = w;
        invW[k] = 1.0f / w;
        yn[1 + k] = Y0[b * NS + k];
    }
    if (tid == 0) yn[0] = T0[b];
    __syncthreads();

    for (int step = 0; step < n_steps; ++step) {
        for (int i = tid; i < ND; i += BD) ycur[i] = yn[i];
        __syncthreads();

        for (int it = 0; it < 2; ++it) {
            // ---- zero accumulators (scalar; odd stride forbids vector) ----
            for (int idx = tid; idx < ND * MSTR; idx += BD)
                (&Mm[0][0])[idx] = 0.0f;
            for (int k = tid; k < NS; k += BD) { wd[k] = 0.0f; uu[k] = 0.0f; vv[k] = 0.0f; }
            if (tid == 0) {
                float Tr = yn[0];
                float Tc = fminf(fmaxf(Tr, 200.0f), 5000.0f);
                sT = Tc;
                sMT = (Tr > 200.0f && Tr < 5000.0f) ? 1.0f : 0.0f;
                sLnT = logf(Tc);
            }
            __syncthreads();

            const float T = sT;
            const float invT = 1.0f / T;
            // ---- per-species thermo ----
            for (int k = tid; k < NS; k += BD) {
                float Yr = yn[1 + k];
                float Yc = fminf(fmaxf(Yr, 0.0f), 1.0f);
                Ycs[k] = Yc;
                mY[k]  = (Yr > 0.0f && Yr < 1.0f) ? 1.0f : 0.0f;
                const float* a = (T < Tmid[k]) ? (nlo + 7 * k) : (nhi + 7 * k);
                float a0 = a[0], a1 = a[1], a2 = a[2], a3 = a[3], a4 = a[4], a5 = a[5];
                float T2 = T * T, T3 = T2 * T, T4 = T2 * T2;
                cpR[k]  = a0 + a1 * T + a2 * T2 + a3 * T3 + a4 * T4;
                float hRT = a0 + a1 * T * 0.5f + a2 * T2 * (1.0f / 3.0f)
                          + a3 * T3 * 0.25f + a4 * T4 * 0.2f + a5 * invT;
                hmol[k] = hRT * RGAS * T;
                dcpR[k] = a1 + 2.0f * a2 * T + 3.0f * a3 * T2 + 4.0f * a4 * T3;
                tmp[k]  = Yc * invW[k];
            }
            __syncthreads();
            if (tid < 32) {
                float s = (lane < NS ? tmp[lane] : 0.0f)
                        + (lane + 32 < NS ? tmp[lane + 32] : 0.0f);
                for (int o = 16; o; o >>= 1) s += __shfl_xor_sync(0xffffffffu, s, o);
                if (lane == 0) {
                    sIMW = s; sInvIMW = 1.0f / s;
                    float rho = P / (RGAS * T * s);
                    sRho = rho; sInvRho = (RGAS * T * s) / P;
                }
            }
            __syncthreads();
            const float rho = sRho, invRho = sInvRho, invIMW = sInvIMW;
            for (int k = tid; k < NS; k += BD) {
                float iw = invW[k];
                float C  = rho * Ycs[k] * iw;
                float Ce = C + 1e-30f;
                Lc[k]  = logf(Ce);
                gC[k]  = C / Ce;
                t0a[k] = rho * iw / Ce;
                Wor[k] = Ws[k] * invRho;
                sm0[k] = -invIMW * iw;
            }
            __syncthreads();

            // ---- reaction pass: rates + exact sensitivities ----
            const float RT = RGAS * T;
            const float invRT = 1.0f / RT;
            for (int j = tid; j < NRX; j += BD) {
                float Aj = rA[j], bj = rB[j], Ej = rE[j];
                float kf = Aj * expf(bj * sLnT - Ej * invRT);
                int nf = g_fcnt[j];
                float sL = 0.0f, Pj = 0.0f;
                for (int e = 0; e < nf; e++) {
                    int k = g_fidx[j][e]; float v = g_fval[j][e];
                    sL += v * Lc[k]; Pj += v * gC[k];
                }
                float r  = kf * expf(sL);
                float rT = (r * invT) * (bj + Ej * invRT - Pj);   // dr/dT (unmasked)
                float rP = r * Pj;
                int nn = g_ncnt[j];
                for (int e = 0; e < nn; e++) {
                    int k = g_nidx[j][e]; float nu = g_nval[j][e];
                    atomicAdd(&wd[k], nu * r);
                    atomicAdd(&uu[k], nu * rP);
                    atomicAdd(&vv[k], nu * rT);
                    float nur = nu * r;
                    for (int e2 = 0; e2 < nf; e2++)
                        atomicAdd(&Mm[k + 1][g_fidx[j][e2] + 1], nur * g_fval[j][e2]);
                }
            }
            __syncthreads();

            // ---- scalar reductions ----
            if (tid < 32) {
                float cp = 0, H = 0, hu = 0, hv = 0, hw = 0, dc = 0;
                for (int k = lane; k < NS; k += 32) {
                    float yw = Ycs[k] * invW[k];
                    cp += yw * cpR[k];
                    H  += hmol[k] * wd[k];
                    hu += hmol[k] * uu[k];
                    hv += hmol[k] * vv[k];
                    hw += cpR[k] * wd[k];
                    dc += yw * dcpR[k];
                }
                for (int o = 16; o; o >>= 1) {
                    cp += __shfl_xor_sync(0xffffffffu, cp, o);
                    H  += __shfl_xor_sync(0xffffffffu, H,  o);
                    hu += __shfl_xor_sync(0xffffffffu, hu, o);
                    hv += __shfl_xor_sync(0xffffffffu, hv, o);
                    hw += __shfl_xor_sync(0xffffffffu, hw, o);
                    dc += __shfl_xor_sync(0xffffffffu, dc, o);
                }
                if (lane == 0) {
                    float cpm = RGAS * cp;
                    sCp = cpm; sHu = hu; sHv = hv;
                    sHTw = RGAS * hw; sDcp = RGAS * dc;
                    float rcp = rho * cpm;
                    sRcp = rcp;
                    sdT = -H / rcp;
                }
            }
            __syncthreads();

            // ---- hQ_m = sum_k h_k * Qraw[k][m] (conflict-free via odd stride) ----
            for (int m = tid; m < NS; m += BD) {
                float s = 0.0f;
                for (int k = 0; k < NS; k++) s += hmol[k] * Mm[k + 1][m + 1];
                hQ[m] = s;
            }
            __syncthreads();

            // ---- build P = dt*J (warp-per-row) and RHS G ----
            const float rcp = sRcp, dTv = sdT, cpm = sCp, huv = sHu;
            const float invCpm = 1.0f / cpm, invRcp = 1.0f / rcp;
            for (int k = wid; k < NS; k += NW) {
                float uk  = uu[k] - wd[k];
                float wok = Wor[k];
                for (int m = lane; m < NS; m += 32) {
                    float q = Mm[k + 1][m + 1];            // Qraw_{km}
                    float J = mY[m] * wok * (uk * sm0[m] + q * t0a[m]);
                    Mm[k + 1][m + 1] = dt * J;
                }
            }
            __syncthreads();
            for (int k = tid; k < NS; k += BD) {
                float Jk0 = sMT * Wor[k] * (vv[k] + wd[k] * invT);
                Mm[k + 1][0] = dt * Jk0;
                float sm0k = sm0[k];
                float J0m = mY[k] * (-(huv * sm0k + hQ[k] * t0a[k]) * invRcp
                                     - dTv * (sm0k + cpR[k] * RGAS * invW[k] * invCpm));
                Mm[0][k + 1] = dt * J0m;
                float fk = wd[k] * Wor[k];
                float g  = yn[1 + k] - ycur[1 + k] - dt * fk;
                gg[1 + k]  = g;
                xsA[1 + k] = g;
            }
            if (tid == 0) {
                float J00 = sMT * (-(sHTw + sHv) / rcp
                                   - dTv * (-invT + sDcp / cpm));
                Mm[0][0] = dt * J00;
                float g0 = yn[0] - ycur[0] - dt * dTv;
                gg[0]  = g0;
                xsA[0] = g0;
            }
            __syncthreads();

            // ---- Richardson solve: x <- G + P x (thread-per-row, no shfl) ----
            // Threads 0..53 (warps 0,1) each own a row; column loop reads
            // Mm[r][c] at stride 55 across lanes -> conflict-free; x[c] is a
            // broadcast. 2-warp named barrier between sweeps.
            if (tid < 64) {
                const int r = tid;
                const bool act = (r < ND);
                float grr = act ? gg[r] : 0.0f;
                #pragma unroll
                for (int m = 0; m < KRICH; m++) {
                    const float* xin = (m & 1) ? xsB : xsA;
                    float*       xout = (m & 1) ? xsA : xsB;
                    if (act) {
                        float s0 = 0.0f, s1 = 0.0f;
                        #pragma unroll
                        for (int c = 0; c < ND; c += 2) {
                            s0 += Mm[r][c]     * xin[c];
                            s1 += Mm[r][c + 1] * xin[c + 1];
                        }
                        xout[r] = grr + s0 + s1;
                    }
                    asm volatile("bar.sync 1, 64;" ::: "memory");
                }
            }
            __syncthreads();
            // KRICH even -> final x in xsA
            for (int i = tid; i < ND; i += BD) yn[i] -= xsA[i];
            __syncthreads();
        } // newton
    } // steps

    for (int i = tid; i < ND; i += BD) out[b * ND + i] = yn[i];
}

extern "C" void kernel_launch(void* const* d_in, const int* in_sizes, int n_in,
                              void* d_out, int out_size) {
    const float* T0  = (const float*)d_in[0];
    const float* P   = (const float*)d_in[1];
    const float* Y0  = (const float*)d_in[2];
    const float* W   = (const float*)d_in[3];
    const float* nlo = (const float*)d_in[4];
    const float* nhi = (const float*)d_in[5];
    const float* Tm  = (const float*)d_in[6];
    const float* A   = (const float*)d_in[7];
    const float* Bc  = (const float*)d_in[8];
    const float* E   = (const float*)d_in[9];
    const float* nf  = (const float*)d_in[10];
    const float* nb  = (const float*)d_in[11];
    const int*   ns  = (const int*)d_in[12];
    const int B = in_sizes[0];

    prep_kernel<<<(NRX + 127) / 128, 128>>>(nf, nb);
    reactor_kernel<<<B, BD>>>(T0, P, Y0, W, nlo, nhi, Tm, A, Bc, E, ns, (float*)d_out);
}